// round 3
// baseline (speedup 1.0000x reference)
#include <cuda_runtime.h>
#include <cstdint>

// Problem constants (fixed shapes from the reference)
#define NNODES 100000
#define NEDGES 1600000
#define DIM    128
#define OUTD   32
#define NGRAPH 512
#define NLAYER 3

// ---------------- scratch (static __device__ — no allocation allowed) -------
__device__ float g_buf [NNODES * DIM];   // h (ping buffer, reused in place)
__device__ float g_hw  [NNODES * DIM];   // h @ W per layer
__device__ float g_agg [NNODES * DIM];   // aggregation target
__device__ float g_deg [NNODES];
__device__ float g_inv [NNODES];         // 1/sqrt(deg+1)
__device__ float g_pool[NGRAPH * DIM];
__device__ float g_dec1[NGRAPH * DIM];

// ---------------- utility kernels -------------------------------------------
__global__ void zero_kernel(float* p, int n) {
    int i = blockIdx.x * blockDim.x + threadIdx.x;
    int stride = gridDim.x * blockDim.x;
    for (; i < n; i += stride) p[i] = 0.0f;
}

__global__ void deg_kernel(const int* __restrict__ dst, int E) {
    int e = blockIdx.x * blockDim.x + threadIdx.x;
    if (e < E) atomicAdd(&g_deg[dst[e]], 1.0f);
}

__global__ void invsqrt_kernel(int n) {
    int i = blockIdx.x * blockDim.x + threadIdx.x;
    if (i < n) g_inv[i] = rsqrtf(g_deg[i] + 1.0f);
}

// ---------------- fused GEMM: out = A[nrows,128] @ W[128,128] ----------------
// MODE 0 (encoder/decoder): out = relu(A@W + b)
// MODE 1 (gcn):             hw = A@W ; agg = hw*self_coef[r] + b[c]
// Block: 256 threads, 64-row tile. SMEM: W (64KB) + A tile (32KB) = 96KB dyn.
template <int MODE>
__global__ void gemm128_kernel(const float* __restrict__ A,
                               const float* __restrict__ W,
                               const float* __restrict__ bias,
                               float* __restrict__ out,
                               float* __restrict__ agg,
                               int nrows)
{
    extern __shared__ float sm[];
    float* Ws = sm;            // [128][128]
    float* As = sm + DIM*DIM;  // [64][128]

    const int tid  = threadIdx.x;
    const int row0 = blockIdx.x * 64;

    // Load W (4096 float4, 16 per thread), coalesced
    {
        const float4* Wd  = (const float4*)W;
        float4*       Wsv = (float4*)Ws;
        #pragma unroll
        for (int i = 0; i < 16; i++) Wsv[tid + 256 * i] = Wd[tid + 256 * i];
    }
    // Load A tile (2048 float4, 8 per thread), OOB rows zero-padded
    {
        const int rvalid = min(nrows - row0, 64);
        const int maxv   = rvalid * (DIM / 4);
        const float4* Ad  = (const float4*)(A + (size_t)row0 * DIM);
        float4*       Asv = (float4*)As;
        #pragma unroll
        for (int i = 0; i < 8; i++) {
            int idx = tid + 256 * i;
            float4 v = make_float4(0.f, 0.f, 0.f, 0.f);
            if (idx < maxv) v = Ad[idx];
            Asv[idx] = v;
        }
    }
    __syncthreads();

    const int tx = tid & 31;   // column group: cols 4*tx .. 4*tx+3
    const int ty = tid >> 5;   // row group: rows ty, ty+8, ..., ty+56

    float acc[8][4];
    #pragma unroll
    for (int i = 0; i < 8; i++)
        #pragma unroll
        for (int j = 0; j < 4; j++) acc[i][j] = 0.f;

    #pragma unroll 4
    for (int k = 0; k < DIM; k++) {
        const float4 w = ((const float4*)(Ws + k * DIM))[tx];
        float a[8];
        #pragma unroll
        for (int i = 0; i < 8; i++) a[i] = As[(ty + 8 * i) * DIM + k];  // broadcast
        #pragma unroll
        for (int i = 0; i < 8; i++) {
            acc[i][0] = fmaf(a[i], w.x, acc[i][0]);
            acc[i][1] = fmaf(a[i], w.y, acc[i][1]);
            acc[i][2] = fmaf(a[i], w.z, acc[i][2]);
            acc[i][3] = fmaf(a[i], w.w, acc[i][3]);
        }
    }

    const float4 b = ((const float4*)bias)[tx];
    #pragma unroll
    for (int i = 0; i < 8; i++) {
        const int r = row0 + ty + 8 * i;
        if (r >= nrows) continue;
        float4 v = make_float4(acc[i][0], acc[i][1], acc[i][2], acc[i][3]);
        if (MODE == 0) {
            v.x = fmaxf(v.x + b.x, 0.f);
            v.y = fmaxf(v.y + b.y, 0.f);
            v.z = fmaxf(v.z + b.z, 0.f);
            v.w = fmaxf(v.w + b.w, 0.f);
            ((float4*)(out + (size_t)r * DIM))[tx] = v;
        } else {
            ((float4*)(out + (size_t)r * DIM))[tx] = v;        // hw (for gather)
            const float sc = g_inv[r] * g_inv[r];              // self coefficient
            float4 g;
            g.x = fmaf(v.x, sc, b.x);
            g.y = fmaf(v.y, sc, b.y);
            g.z = fmaf(v.z, sc, b.z);
            g.w = fmaf(v.w, sc, b.w);
            ((float4*)(agg + (size_t)r * DIM))[tx] = g;        // agg init
        }
    }
}

// ---------------- edge scatter: agg[dst] += hw[src] * c_src*c_dst ------------
// One warp per edge: 32 lanes x float4 = the full 128-float row, coalesced.
__global__ void scatter_kernel(const float* __restrict__ hw,
                               const int* __restrict__ src,
                               const int* __restrict__ dst,
                               float* __restrict__ agg, int E)
{
    const int warp = (blockIdx.x * blockDim.x + threadIdx.x) >> 5;
    const int lane = threadIdx.x & 31;
    if (warp >= E) return;
    const int s = __ldg(src + warp);
    const int d = __ldg(dst + warp);
    const float coef = g_inv[s] * g_inv[d];
    float4 v = ((const float4*)(hw + (size_t)s * DIM))[lane];
    v.x *= coef; v.y *= coef; v.z *= coef; v.w *= coef;
    float* a = agg + (size_t)d * DIM + lane * 4;
    asm volatile("red.global.add.v4.f32 [%0], {%1,%2,%3,%4};"
                 :: "l"(a), "f"(v.x), "f"(v.y), "f"(v.z), "f"(v.w)
                 : "memory");
}

// ---------------- h = relu(agg) ----------------------------------------------
__global__ void relu_copy_kernel(const float* __restrict__ in,
                                 float* __restrict__ out, int n4)
{
    int i = blockIdx.x * blockDim.x + threadIdx.x;
    int stride = gridDim.x * blockDim.x;
    for (; i < n4; i += stride) {
        float4 v = ((const float4*)in)[i];
        v.x = fmaxf(v.x, 0.f); v.y = fmaxf(v.y, 0.f);
        v.z = fmaxf(v.z, 0.f); v.w = fmaxf(v.w, 0.f);
        ((float4*)out)[i] = v;
    }
}

// ---------------- global add pool: pool[batch[i]] += h[i] --------------------
__global__ void pool_kernel(const float* __restrict__ h,
                            const int* __restrict__ batch, int N)
{
    const int node = (blockIdx.x * blockDim.x + threadIdx.x) >> 5;
    const int lane = threadIdx.x & 31;
    if (node >= N) return;
    const int g = __ldg(batch + node);
    const float4 v = ((const float4*)(h + (size_t)node * DIM))[lane];
    float* p = g_pool + (size_t)g * DIM + lane * 4;
    asm volatile("red.global.add.v4.f32 [%0], {%1,%2,%3,%4};"
                 :: "l"(p), "f"(v.x), "f"(v.y), "f"(v.z), "f"(v.w)
                 : "memory");
}

// ---------------- decoder layer 2: out[g][o] = dec1[g] . W2[:,o] + b2 --------
__global__ void dec2_kernel(const float* __restrict__ dec1,
                            const float* __restrict__ W2,
                            const float* __restrict__ b2,
                            float* __restrict__ out)
{
    const int idx = blockIdx.x * blockDim.x + threadIdx.x;
    if (idx >= NGRAPH * OUTD) return;
    const int g = idx >> 5;        // OUTD == 32
    const int o = idx & 31;
    const float* row = dec1 + (size_t)g * DIM;
    float s = b2[o];
    #pragma unroll 8
    for (int k = 0; k < DIM; k++) s = fmaf(row[k], W2[k * OUTD + o], s);
    out[idx] = s;
}

// ---------------- host launch ------------------------------------------------
extern "C" void kernel_launch(void* const* d_in, const int* in_sizes, int n_in,
                              void* d_out, int out_size)
{
    const float* x       = (const float*)d_in[0];
    const int*   eidx    = (const int*)  d_in[1];
    const int*   batch   = (const int*)  d_in[2];
    const float* enc_W1  = (const float*)d_in[3];
    const float* enc_b1  = (const float*)d_in[4];
    const float* enc_W2  = (const float*)d_in[5];
    const float* enc_b2  = (const float*)d_in[6];
    const float* gcn_W   = (const float*)d_in[7];
    const float* gcn_b   = (const float*)d_in[8];
    const float* dec_W1  = (const float*)d_in[9];
    const float* dec_b1  = (const float*)d_in[10];
    const float* dec_W2  = (const float*)d_in[11];
    const float* dec_b2  = (const float*)d_in[12];

    const int N = in_sizes[0] / DIM;      // 100000
    const int E = in_sizes[1] / 2;        // 1600000
    const int* src = eidx;
    const int* dst = eidx + E;

    // Resolve device-symbol addresses (host-side, not captured as work)
    float *bufp, *hwp, *aggp, *degp, *poolp, *dec1p;
    cudaGetSymbolAddress((void**)&bufp,  g_buf);
    cudaGetSymbolAddress((void**)&hwp,   g_hw);
    cudaGetSymbolAddress((void**)&aggp,  g_agg);
    cudaGetSymbolAddress((void**)&degp,  g_deg);
    cudaGetSymbolAddress((void**)&poolp, g_pool);
    cudaGetSymbolAddress((void**)&dec1p, g_dec1);

    // Opt into 96KB dynamic SMEM for the GEMM kernels (idempotent)
    const int smem = (DIM * DIM + 64 * DIM) * (int)sizeof(float);  // 98304
    cudaFuncSetAttribute(gemm128_kernel<0>,
                         cudaFuncAttributeMaxDynamicSharedMemorySize, smem);
    cudaFuncSetAttribute(gemm128_kernel<1>,
                         cudaFuncAttributeMaxDynamicSharedMemorySize, smem);

    const int gemm_blocks = (N + 63) / 64;

    // 1) degrees + normalization coefficients
    zero_kernel<<<256, 256>>>(degp, N);
    deg_kernel<<<(E + 255) / 256, 256>>>(dst, E);
    invsqrt_kernel<<<(N + 255) / 256, 256>>>(N);

    // 2) encoder MLP (in place after first GEMM)
    gemm128_kernel<0><<<gemm_blocks, 256, smem>>>(x,    enc_W1, enc_b1, bufp, nullptr, N);
    gemm128_kernel<0><<<gemm_blocks, 256, smem>>>(bufp, enc_W2, enc_b2, bufp, nullptr, N);

    // 3) GCN layers
    const int scatter_blocks = (E * 32 + 255) / 256;
    for (int l = 0; l < NLAYER; l++) {
        gemm128_kernel<1><<<gemm_blocks, 256, smem>>>(
            bufp, gcn_W + (size_t)l * DIM * DIM, gcn_b + (size_t)l * DIM,
            hwp, aggp, N);
        scatter_kernel<<<scatter_blocks, 256>>>(hwp, src, dst, aggp, E);
        relu_copy_kernel<<<2048, 256>>>(aggp, bufp, N * DIM / 4);
    }

    // 4) global add pool
    zero_kernel<<<256, 256>>>(poolp, NGRAPH * DIM);
    pool_kernel<<<(N * 32 + 255) / 256, 256>>>(bufp, batch, N);

    // 5) decoder
    gemm128_kernel<0><<<(NGRAPH + 63) / 64, 256, smem>>>(poolp, dec_W1, dec_b1, dec1p, nullptr, NGRAPH);
    dec2_kernel<<<(NGRAPH * OUTD + 255) / 256, 256>>>(dec1p, dec_W2, dec_b2, (float*)d_out);
}

// round 5
// speedup vs baseline: 1.2128x; 1.2128x over previous
#include <cuda_runtime.h>
#include <cuda_bf16.h>
#include <cstdint>

#define NNODES 100000
#define NEDGES 1600000
#define DIM    128
#define OUTD   32
#define NGRAPH 512
#define NLAYER 3
#define NMAT   6          // enc1, enc2, gcn0, gcn1, gcn2, dec1

// ---------------- scratch (static __device__ — no allocation allowed) -------
__device__ float g_buf [NNODES * DIM];
__device__ float g_hw  [NNODES * DIM];
__device__ float g_agg [NNODES * DIM];
__device__ float g_deg [NNODES];
__device__ float g_inv [NNODES];
__device__ float g_pool[NGRAPH * DIM];
__device__ float g_dec1[NGRAPH * DIM];
// bf16 weight images, B-operand layout: Bimg[n][k] = W[k][n], linear [n*128+k]
__device__ __nv_bfloat16 g_whi[NMAT * DIM * DIM];
__device__ __nv_bfloat16 g_wlo[NMAT * DIM * DIM];

// ==================== helpers ===============================================
__device__ __forceinline__ uint32_t smem_u32(const void* p) {
    uint32_t a;
    asm("{ .reg .u64 t; cvta.to.shared.u64 t, %1; cvt.u32.u64 %0, t; }"
        : "=r"(a) : "l"(p));
    return a;
}

__device__ __forceinline__ void ldsm4(uint32_t* r, uint32_t addr) {
    asm volatile("ldmatrix.sync.aligned.m8n8.x4.shared.b16 {%0,%1,%2,%3}, [%4];"
                 : "=r"(r[0]), "=r"(r[1]), "=r"(r[2]), "=r"(r[3]) : "r"(addr));
}

__device__ __forceinline__ void mma16816(float* c, const uint32_t* a,
                                         uint32_t b0, uint32_t b1) {
    asm volatile(
        "mma.sync.aligned.m16n8k16.row.col.f32.bf16.bf16.f32 "
        "{%0,%1,%2,%3}, {%4,%5,%6,%7}, {%8,%9}, {%0,%1,%2,%3};"
        : "+f"(c[0]), "+f"(c[1]), "+f"(c[2]), "+f"(c[3])
        : "r"(a[0]), "r"(a[1]), "r"(a[2]), "r"(a[3]), "r"(b0), "r"(b1));
}

// ==================== weight prep: fp32 W -> bf16 hi/lo transposed images ====
struct WPtrs { const float* w[NMAT]; };

__global__ void prepw_kernel(WPtrs wp) {
    const int mat = blockIdx.x >> 6;
    const int i0  = (blockIdx.x & 63) * 256 + threadIdx.x;   // = n*128+k
    const float* W = wp.w[mat];
    const int n = i0 >> 7, k = i0 & 127;
    const float w = W[k * DIM + n];
    const __nv_bfloat16 h = __float2bfloat16_rn(w);
    const __nv_bfloat16 l = __float2bfloat16_rn(w - __bfloat162float(h));
    g_whi[mat * DIM * DIM + i0] = h;
    g_wlo[mat * DIM * DIM + i0] = l;
}

// ==================== mma.sync GEMM: C[128,128] tile = A @ W =================
// MODE 0: out = relu(C + b)
// MODE 1: hw = C ; agg = C*inv[r]^2 + b
// RELU_IN: relu(A) while converting to bf16 (feeds GCN layers 1,2 from agg)
// SMEM: bias[128] at 0; padded bf16 tiles (stride 136 elems = 272 B):
//   A_hi, A_lo, B_hi, B_lo at 34816 B each.
#define TSTRIDE 272                 // bytes per padded row (136 bf16)
#define TILE_B  (128 * TSTRIDE)     // 34816
#define AH_OFF  1024
#define AL_OFF  (AH_OFF + TILE_B)
#define BH_OFF  (AL_OFF + TILE_B)
#define BL_OFF  (BH_OFF + TILE_B)
#define SMEM_BYTES (BL_OFF + TILE_B)

template <int MODE, bool RELU_IN>
__global__ __launch_bounds__(256, 1)
void mmagemm_kernel(const float* __restrict__ A,
                    const __nv_bfloat16* __restrict__ Whi,
                    const __nv_bfloat16* __restrict__ Wlo,
                    const float* __restrict__ bias,
                    float* __restrict__ out,
                    float* __restrict__ agg,
                    int nrows)
{
    extern __shared__ char smem[];
    const uint32_t sbase = smem_u32(smem);
    const int tid  = threadIdx.x;
    const int wid  = tid >> 5;
    const int lane = tid & 31;
    const int row0 = blockIdx.x * 128;
    const int rvalid = min(nrows - row0, 128);

    if (tid < 128) ((float*)smem)[tid] = bias[tid];

    // ---- stage B hi/lo (linear global -> padded smem), 2048 float4 each ----
    {
        const float4* sh = (const float4*)Whi;
        const float4* sl = (const float4*)Wlo;
        #pragma unroll
        for (int it = 0; it < 8; it++) {
            const int idx = tid + 256 * it;
            const int r = idx >> 4, c = idx & 15;
            *(float4*)(smem + BH_OFF + r * TSTRIDE + c * 16) = sh[idx];
            *(float4*)(smem + BL_OFF + r * TSTRIDE + c * 16) = sl[idx];
        }
    }
    // ---- stage A: fp32 -> bf16 hi/lo (optionally relu), 4096 float4 --------
    {
        #pragma unroll
        for (int it = 0; it < 16; it++) {
            const int idx = tid + 256 * it;
            const int m = idx >> 5, c4 = idx & 31;
            float4 v = make_float4(0.f, 0.f, 0.f, 0.f);
            if (m < rvalid) v = ((const float4*)(A + (size_t)(row0 + m) * DIM))[c4];
            if (RELU_IN) {
                v.x = fmaxf(v.x, 0.f); v.y = fmaxf(v.y, 0.f);
                v.z = fmaxf(v.z, 0.f); v.w = fmaxf(v.w, 0.f);
            }
            const __nv_bfloat16 h0 = __float2bfloat16_rn(v.x);
            const __nv_bfloat16 h1 = __float2bfloat16_rn(v.y);
            const __nv_bfloat16 h2 = __float2bfloat16_rn(v.z);
            const __nv_bfloat16 h3 = __float2bfloat16_rn(v.w);
            const __nv_bfloat16 l0 = __float2bfloat16_rn(v.x - __bfloat162float(h0));
            const __nv_bfloat16 l1 = __float2bfloat16_rn(v.y - __bfloat162float(h1));
            const __nv_bfloat16 l2 = __float2bfloat16_rn(v.z - __bfloat162float(h2));
            const __nv_bfloat16 l3 = __float2bfloat16_rn(v.w - __bfloat162float(h3));
            uint2 hp, lp;
            hp.x = ((uint32_t)__bfloat16_as_ushort(h1) << 16) | __bfloat16_as_ushort(h0);
            hp.y = ((uint32_t)__bfloat16_as_ushort(h3) << 16) | __bfloat16_as_ushort(h2);
            lp.x = ((uint32_t)__bfloat16_as_ushort(l1) << 16) | __bfloat16_as_ushort(l0);
            lp.y = ((uint32_t)__bfloat16_as_ushort(l3) << 16) | __bfloat16_as_ushort(l2);
            const uint32_t off = (uint32_t)m * TSTRIDE + (uint32_t)c4 * 8;
            *(uint2*)(smem + AH_OFF + off) = hp;
            *(uint2*)(smem + AL_OFF + off) = lp;
        }
    }
    __syncthreads();

    // ---- warp tiling: warp_m in [0,4) rows*32, warp_n in [0,2) cols*64 -----
    const int warp_m = wid & 3;
    const int warp_n = wid >> 2;
    const int gid = lane >> 2;     // group of 4
    const int tig = lane & 3;

    // per-lane ldmatrix base addresses (byte offsets inside tiles)
    // A x4 covers m16 x k16: matrices (m0-7,k0-7),(m8-15,k0-7),(m0-7,k8-15),(m8-15,k8-15)
    const uint32_t a_off = (uint32_t)(warp_m * 32 + (lane & 7) + ((lane >> 3) & 1) * 8) * TSTRIDE
                         + (uint32_t)(lane >> 4) * 16;
    // B x4 covers n16 x k16: matrices (n0-7,k0-7),(n0-7,k8-15),(n8-15,k0-7),(n8-15,k8-15)
    const uint32_t b_off = (uint32_t)(warp_n * 64 + (lane & 7) + (lane >> 4) * 8) * TSTRIDE
                         + (uint32_t)((lane >> 3) & 1) * 16;
    const uint32_t a_hi = sbase + AH_OFF + a_off;
    const uint32_t a_lo = sbase + AL_OFF + a_off;
    const uint32_t b_hi = sbase + BH_OFF + b_off;
    const uint32_t b_lo = sbase + BL_OFF + b_off;

    float acc[2][8][4];
    #pragma unroll
    for (int i = 0; i < 2; i++)
        #pragma unroll
        for (int j = 0; j < 8; j++)
            #pragma unroll
            for (int q = 0; q < 4; q++) acc[i][j][q] = 0.f;

    #pragma unroll
    for (int kc = 0; kc < 8; kc++) {
        const uint32_t kb = (uint32_t)kc * 32;   // 16 bf16 = 32 bytes
        uint32_t ah0[4], ah1[4], al0[4], al1[4];
        ldsm4(ah0, a_hi + kb);
        ldsm4(ah1, a_hi + 16 * TSTRIDE + kb);
        ldsm4(al0, a_lo + kb);
        ldsm4(al1, a_lo + 16 * TSTRIDE + kb);
        #pragma unroll
        for (int g = 0; g < 4; g++) {
            uint32_t bh[4], bl[4];
            ldsm4(bh, b_hi + (uint32_t)g * 16 * TSTRIDE + kb);
            ldsm4(bl, b_lo + (uint32_t)g * 16 * TSTRIDE + kb);
            const int n0 = 2 * g, n1 = 2 * g + 1;
            // pass hh
            mma16816(acc[0][n0], ah0, bh[0], bh[1]);
            mma16816(acc[0][n1], ah0, bh[2], bh[3]);
            mma16816(acc[1][n0], ah1, bh[0], bh[1]);
            mma16816(acc[1][n1], ah1, bh[2], bh[3]);
            // pass hl
            mma16816(acc[0][n0], ah0, bl[0], bl[1]);
            mma16816(acc[0][n1], ah0, bl[2], bl[3]);
            mma16816(acc[1][n0], ah1, bl[0], bl[1]);
            mma16816(acc[1][n1], ah1, bl[2], bl[3]);
            // pass lh
            mma16816(acc[0][n0], al0, bh[0], bh[1]);
            mma16816(acc[0][n1], al0, bh[2], bh[3]);
            mma16816(acc[1][n0], al1, bh[0], bh[1]);
            mma16816(acc[1][n1], al1, bh[2], bh[3]);
        }
    }

    // ---- epilogue: fragment c = {(gid,2tig),(gid,2tig+1),(gid+8,2tig),(gid+8,+1)}
    const float* sbias = (const float*)smem;
    #pragma unroll
    for (int mt = 0; mt < 2; mt++) {
        #pragma unroll
        for (int h = 0; h < 2; h++) {
            const int rloc = warp_m * 32 + mt * 16 + h * 8 + gid;
            if (rloc >= rvalid) continue;
            const int r = row0 + rloc;
            float sc = 0.f;
            if (MODE == 1) { const float iv = g_inv[r]; sc = iv * iv; }
            #pragma unroll
            for (int nt = 0; nt < 8; nt++) {
                const int col = warp_n * 64 + nt * 8 + 2 * tig;
                const float c0 = acc[mt][nt][h * 2 + 0];
                const float c1 = acc[mt][nt][h * 2 + 1];
                const float b0 = sbias[col], b1 = sbias[col + 1];
                if (MODE == 0) {
                    float2 v = make_float2(fmaxf(c0 + b0, 0.f), fmaxf(c1 + b1, 0.f));
                    *(float2*)(out + (size_t)r * DIM + col) = v;
                } else {
                    *(float2*)(out + (size_t)r * DIM + col) = make_float2(c0, c1);
                    float2 gg = make_float2(fmaf(c0, sc, b0), fmaf(c1, sc, b1));
                    *(float2*)(agg + (size_t)r * DIM + col) = gg;
                }
            }
        }
    }
}

// ==================== graph kernels =========================================
__global__ void zero_kernel(float* p, int n) {
    int i = blockIdx.x * blockDim.x + threadIdx.x;
    int stride = gridDim.x * blockDim.x;
    for (; i < n; i += stride) p[i] = 0.0f;
}

__global__ void deg_kernel(const int* __restrict__ dst, int E) {
    int e = blockIdx.x * blockDim.x + threadIdx.x;
    if (e < E) atomicAdd(&g_deg[dst[e]], 1.0f);
}

__global__ void invsqrt_kernel(int n) {
    int i = blockIdx.x * blockDim.x + threadIdx.x;
    if (i < n) g_inv[i] = rsqrtf(g_deg[i] + 1.0f);
}

__global__ void scatter_kernel(const float* __restrict__ hw,
                               const int* __restrict__ src,
                               const int* __restrict__ dst,
                               float* __restrict__ agg, int E)
{
    const int warp = (blockIdx.x * blockDim.x + threadIdx.x) >> 5;
    const int lane = threadIdx.x & 31;
    if (warp >= E) return;
    const int s = __ldg(src + warp);
    const int d = __ldg(dst + warp);
    const float coef = g_inv[s] * g_inv[d];
    float4 v = ((const float4*)(hw + (size_t)s * DIM))[lane];
    v.x *= coef; v.y *= coef; v.z *= coef; v.w *= coef;
    float* a = agg + (size_t)d * DIM + lane * 4;
    asm volatile("red.global.add.v4.f32 [%0], {%1,%2,%3,%4};"
                 :: "l"(a), "f"(v.x), "f"(v.y), "f"(v.z), "f"(v.w)
                 : "memory");
}

// pool[batch[i]] += relu(agg[i])
__global__ void pool_kernel(const float* __restrict__ h,
                            const int* __restrict__ batch, int N)
{
    const int node = (blockIdx.x * blockDim.x + threadIdx.x) >> 5;
    const int lane = threadIdx.x & 31;
    if (node >= N) return;
    const int g = __ldg(batch + node);
    float4 v = ((const float4*)(h + (size_t)node * DIM))[lane];
    v.x = fmaxf(v.x, 0.f); v.y = fmaxf(v.y, 0.f);
    v.z = fmaxf(v.z, 0.f); v.w = fmaxf(v.w, 0.f);
    float* p = g_pool + (size_t)g * DIM + lane * 4;
    asm volatile("red.global.add.v4.f32 [%0], {%1,%2,%3,%4};"
                 :: "l"(p), "f"(v.x), "f"(v.y), "f"(v.z), "f"(v.w)
                 : "memory");
}

__global__ void dec2_kernel(const float* __restrict__ dec1,
                            const float* __restrict__ W2,
                            const float* __restrict__ b2,
                            float* __restrict__ out)
{
    const int idx = blockIdx.x * blockDim.x + threadIdx.x;
    if (idx >= NGRAPH * OUTD) return;
    const int g = idx >> 5;
    const int o = idx & 31;
    const float* row = dec1 + (size_t)g * DIM;
    float s = b2[o];
    #pragma unroll 8
    for (int k = 0; k < DIM; k++) s = fmaf(row[k], W2[k * OUTD + o], s);
    out[idx] = s;
}

// ==================== host launch ===========================================
extern "C" void kernel_launch(void* const* d_in, const int* in_sizes, int n_in,
                              void* d_out, int out_size)
{
    const float* x       = (const float*)d_in[0];
    const int*   eidx    = (const int*)  d_in[1];
    const int*   batch   = (const int*)  d_in[2];
    const float* enc_W1  = (const float*)d_in[3];
    const float* enc_b1  = (const float*)d_in[4];
    const float* enc_W2  = (const float*)d_in[5];
    const float* enc_b2  = (const float*)d_in[6];
    const float* gcn_W   = (const float*)d_in[7];
    const float* gcn_b   = (const float*)d_in[8];
    const float* dec_W1  = (const float*)d_in[9];
    const float* dec_b1  = (const float*)d_in[10];
    const float* dec_W2  = (const float*)d_in[11];
    const float* dec_b2  = (const float*)d_in[12];

    const int N = in_sizes[0] / DIM;
    const int E = in_sizes[1] / 2;
    const int* src = eidx;
    const int* dst = eidx + E;

    float *bufp, *hwp, *aggp, *degp, *poolp, *dec1p;
    __nv_bfloat16 *whip, *wlop;
    cudaGetSymbolAddress((void**)&bufp,  g_buf);
    cudaGetSymbolAddress((void**)&hwp,   g_hw);
    cudaGetSymbolAddress((void**)&aggp,  g_agg);
    cudaGetSymbolAddress((void**)&degp,  g_deg);
    cudaGetSymbolAddress((void**)&poolp, g_pool);
    cudaGetSymbolAddress((void**)&dec1p, g_dec1);
    cudaGetSymbolAddress((void**)&whip,  g_whi);
    cudaGetSymbolAddress((void**)&wlop,  g_wlo);

    cudaFuncSetAttribute(mmagemm_kernel<0,false>,
                         cudaFuncAttributeMaxDynamicSharedMemorySize, SMEM_BYTES);
    cudaFuncSetAttribute(mmagemm_kernel<1,false>,
                         cudaFuncAttributeMaxDynamicSharedMemorySize, SMEM_BYTES);
    cudaFuncSetAttribute(mmagemm_kernel<1,true>,
                         cudaFuncAttributeMaxDynamicSharedMemorySize, SMEM_BYTES);

    const int WSZ = DIM * DIM;
    const int gemm_blocks = (N + 127) / 128;

    // 1) degrees + normalization + weight prep
    zero_kernel<<<256, 256>>>(degp, N);
    deg_kernel<<<(E + 255) / 256, 256>>>(dst, E);
    invsqrt_kernel<<<(N + 255) / 256, 256>>>(N);
    {
        WPtrs wp;
        wp.w[0] = enc_W1; wp.w[1] = enc_W2;
        wp.w[2] = gcn_W;  wp.w[3] = gcn_W + WSZ; wp.w[4] = gcn_W + 2 * WSZ;
        wp.w[5] = dec_W1;
        prepw_kernel<<<NMAT * 64, 256>>>(wp);
    }

    // 2) encoder MLP (tensor GEMMs, relu fused in epilogue)
    mmagemm_kernel<0,false><<<gemm_blocks, 256, SMEM_BYTES>>>(
        x, whip + 0 * WSZ, wlop + 0 * WSZ, enc_b1, bufp, nullptr, N);
    mmagemm_kernel<0,false><<<gemm_blocks, 256, SMEM_BYTES>>>(
        bufp, whip + 1 * WSZ, wlop + 1 * WSZ, enc_b2, bufp, nullptr, N);

    // 3) GCN layers: GEMM (agg pre-init fused) -> edge scatter; relu fused into
    //    the next GEMM's A conversion / the pool kernel.
    const int scatter_blocks = (E * 32 + 255) / 256;
    for (int l = 0; l < NLAYER; l++) {
        if (l == 0)
            mmagemm_kernel<1,false><<<gemm_blocks, 256, SMEM_BYTES>>>(
                bufp, whip + (2 + l) * WSZ, wlop + (2 + l) * WSZ,
                gcn_b + (size_t)l * DIM, hwp, aggp, N);
        else
            mmagemm_kernel<1,true><<<gemm_blocks, 256, SMEM_BYTES>>>(
                aggp, whip + (2 + l) * WSZ, wlop + (2 + l) * WSZ,
                gcn_b + (size_t)l * DIM, hwp, aggp, N);
        scatter_kernel<<<scatter_blocks, 256>>>(hwp, src, dst, aggp, E);
    }

    // 4) global add pool (relu on read)
    zero_kernel<<<256, 256>>>(poolp, NGRAPH * DIM);
    pool_kernel<<<(N * 32 + 255) / 256, 256>>>(aggp, batch, N);

    // 5) decoder
    mmagemm_kernel<0,false><<<(NGRAPH + 127) / 128, 256, SMEM_BYTES>>>(
        poolp, whip + 5 * WSZ, wlop + 5 * WSZ, dec_b1, dec1p, nullptr, NGRAPH);
    dec2_kernel<<<(NGRAPH * OUTD + 255) / 256, 256>>>(dec1p, dec_W2, dec_b2, (float*)d_out);
}

// round 7
// speedup vs baseline: 1.5953x; 1.3154x over previous
#include <cuda_runtime.h>
#include <cuda_bf16.h>
#include <cstdint>

#define NNODES 100000
#define NEDGES 1600000
#define DIM    128
#define OUTD   32
#define NGRAPH 512
#define NLAYER 3
#define NMAT   6          // enc1, enc2, gcn0, gcn1, gcn2, dec1

// ---------------- scratch (static __device__ — no allocation allowed) -------
__device__ float g_buf [NNODES * DIM];
__device__ float g_hw  [NNODES * DIM];
__device__ float g_agg [NNODES * DIM];
__device__ float g_inv [NNODES];
__device__ float g_pool[NGRAPH * DIM];
__device__ float g_dec1[NGRAPH * DIM];
__device__ int   g_cnt [NNODES];
__device__ int   g_off [NNODES + 1];
__device__ int   g_cur [NNODES];
__device__ int   g_gstart[NGRAPH + 1];
__device__ int2  g_csr [NEDGES];          // {src, bits(inv[src])} binned by dst
// bf16 weight images, B-operand layout: Bimg[n][k] = W[k][n], linear [n*128+k]
__device__ __nv_bfloat16 g_whi[NMAT * DIM * DIM];
__device__ __nv_bfloat16 g_wlo[NMAT * DIM * DIM];

// ==================== helpers ===============================================
__device__ __forceinline__ uint32_t smem_u32(const void* p) {
    uint32_t a;
    asm("{ .reg .u64 t; cvta.to.shared.u64 t, %1; cvt.u32.u64 %0, t; }"
        : "=r"(a) : "l"(p));
    return a;
}

__device__ __forceinline__ void ldsm4(uint32_t* r, uint32_t addr) {
    asm volatile("ldmatrix.sync.aligned.m8n8.x4.shared.b16 {%0,%1,%2,%3}, [%4];"
                 : "=r"(r[0]), "=r"(r[1]), "=r"(r[2]), "=r"(r[3]) : "r"(addr));
}

__device__ __forceinline__ void mma16816(float* c, const uint32_t* a,
                                         uint32_t b0, uint32_t b1) {
    asm volatile(
        "mma.sync.aligned.m16n8k16.row.col.f32.bf16.bf16.f32 "
        "{%0,%1,%2,%3}, {%4,%5,%6,%7}, {%8,%9}, {%0,%1,%2,%3};"
        : "+f"(c[0]), "+f"(c[1]), "+f"(c[2]), "+f"(c[3])
        : "r"(a[0]), "r"(a[1]), "r"(a[2]), "r"(a[3]), "r"(b0), "r"(b1));
}

// ==================== weight prep: fp32 W -> bf16 hi/lo transposed images ====
struct WPtrs { const float* w[NMAT]; };

__global__ void prepw_kernel(WPtrs wp) {
    const int mat = blockIdx.x >> 6;
    const int i0  = (blockIdx.x & 63) * 256 + threadIdx.x;   // = n*128+k
    const float* W = wp.w[mat];
    const int n = i0 >> 7, k = i0 & 127;
    const float w = W[k * DIM + n];
    const __nv_bfloat16 h = __float2bfloat16_rn(w);
    const __nv_bfloat16 l = __float2bfloat16_rn(w - __bfloat162float(h));
    g_whi[mat * DIM * DIM + i0] = h;
    g_wlo[mat * DIM * DIM + i0] = l;
}

// ==================== CSR build =============================================
__global__ void zero_cnt_kernel() {
    int i = blockIdx.x * blockDim.x + threadIdx.x;
    if (i < NNODES) g_cnt[i] = 0;
}

__global__ void hist_kernel(const int* __restrict__ dst, int E) {
    int e = blockIdx.x * blockDim.x + threadIdx.x;
    if (e < E) atomicAdd(&g_cnt[dst[e]], 1);
}

__global__ void invsqrt_kernel(int n) {
    int i = blockIdx.x * blockDim.x + threadIdx.x;
    if (i < n) g_inv[i] = rsqrtf((float)g_cnt[i] + 1.0f);
}

// single-block chunked exclusive scan: g_cnt -> g_off (+g_cur copy)
__global__ void scan_kernel() {
    __shared__ int ssum[1024];
    const int t = threadIdx.x;
    const int chunk = (NNODES + 1023) / 1024;     // 98
    const int lo = t * chunk;
    const int hi = min(lo + chunk, NNODES);
    int s = 0;
    for (int i = lo; i < hi; i++) s += g_cnt[i];
    ssum[t] = s;
    __syncthreads();
    for (int d = 1; d < 1024; d <<= 1) {
        int v = (t >= d) ? ssum[t - d] : 0;
        __syncthreads();
        ssum[t] += v;
        __syncthreads();
    }
    int run = (t == 0) ? 0 : ssum[t - 1];
    for (int i = lo; i < hi; i++) {
        int c = g_cnt[i];
        g_off[i] = run;
        g_cur[i] = run;
        run += c;
    }
    if (t == 1023) g_off[NNODES] = run;
}

__global__ void bin_kernel(const int* __restrict__ src,
                           const int* __restrict__ dst, int E) {
    int e = blockIdx.x * blockDim.x + threadIdx.x;
    if (e >= E) return;
    const int s = src[e], d = dst[e];
    const int pos = atomicAdd(&g_cur[d], 1);
    g_csr[pos] = make_int2(s, __float_as_int(g_inv[s]));
}

// ==================== mma.sync GEMM: C[128,128] tile = A @ W =================
// MODE 0: out = relu(C + b)
// MODE 1: hw = C ; agg = C*inv[r]^2 + b
// RELU_IN: relu(A) while converting to bf16
#define TSTRIDE 272                 // bytes per padded row (136 bf16)
#define TILE_B  (128 * TSTRIDE)     // 34816
#define AH_OFF  1024
#define AL_OFF  (AH_OFF + TILE_B)
#define BH_OFF  (AL_OFF + TILE_B)
#define BL_OFF  (BH_OFF + TILE_B)
#define SMEM_BYTES (BL_OFF + TILE_B)

template <int MODE, bool RELU_IN>
__global__ __launch_bounds__(256, 1)
void mmagemm_kernel(const float* __restrict__ A,
                    const __nv_bfloat16* __restrict__ Whi,
                    const __nv_bfloat16* __restrict__ Wlo,
                    const float* __restrict__ bias,
                    float* __restrict__ out,
                    float* __restrict__ agg,
                    int nrows)
{
    extern __shared__ char smem[];
    const uint32_t sbase = smem_u32(smem);
    const int tid  = threadIdx.x;
    const int wid  = tid >> 5;
    const int lane = tid & 31;
    const int row0 = blockIdx.x * 128;
    const int rvalid = min(nrows - row0, 128);

    if (tid < 128) ((float*)smem)[tid] = bias[tid];

    // stage B hi/lo
    {
        const float4* sh = (const float4*)Whi;
        const float4* sl = (const float4*)Wlo;
        #pragma unroll
        for (int it = 0; it < 8; it++) {
            const int idx = tid + 256 * it;
            const int r = idx >> 4, c = idx & 15;
            *(float4*)(smem + BH_OFF + r * TSTRIDE + c * 16) = sh[idx];
            *(float4*)(smem + BL_OFF + r * TSTRIDE + c * 16) = sl[idx];
        }
    }
    // stage A: fp32 -> bf16 hi/lo (optionally relu)
    {
        #pragma unroll
        for (int it = 0; it < 16; it++) {
            const int idx = tid + 256 * it;
            const int m = idx >> 5, c4 = idx & 31;
            float4 v = make_float4(0.f, 0.f, 0.f, 0.f);
            if (m < rvalid) v = ((const float4*)(A + (size_t)(row0 + m) * DIM))[c4];
            if (RELU_IN) {
                v.x = fmaxf(v.x, 0.f); v.y = fmaxf(v.y, 0.f);
                v.z = fmaxf(v.z, 0.f); v.w = fmaxf(v.w, 0.f);
            }
            const __nv_bfloat16 h0 = __float2bfloat16_rn(v.x);
            const __nv_bfloat16 h1 = __float2bfloat16_rn(v.y);
            const __nv_bfloat16 h2 = __float2bfloat16_rn(v.z);
            const __nv_bfloat16 h3 = __float2bfloat16_rn(v.w);
            const __nv_bfloat16 l0 = __float2bfloat16_rn(v.x - __bfloat162float(h0));
            const __nv_bfloat16 l1 = __float2bfloat16_rn(v.y - __bfloat162float(h1));
            const __nv_bfloat16 l2 = __float2bfloat16_rn(v.z - __bfloat162float(h2));
            const __nv_bfloat16 l3 = __float2bfloat16_rn(v.w - __bfloat162float(h3));
            uint2 hp, lp;
            hp.x = ((uint32_t)__bfloat16_as_ushort(h1) << 16) | __bfloat16_as_ushort(h0);
            hp.y = ((uint32_t)__bfloat16_as_ushort(h3) << 16) | __bfloat16_as_ushort(h2);
            lp.x = ((uint32_t)__bfloat16_as_ushort(l1) << 16) | __bfloat16_as_ushort(l0);
            lp.y = ((uint32_t)__bfloat16_as_ushort(l3) << 16) | __bfloat16_as_ushort(l2);
            const uint32_t off = (uint32_t)m * TSTRIDE + (uint32_t)c4 * 8;
            *(uint2*)(smem + AH_OFF + off) = hp;
            *(uint2*)(smem + AL_OFF + off) = lp;
        }
    }
    __syncthreads();

    const int warp_m = wid & 3;
    const int warp_n = wid >> 2;
    const int gid = lane >> 2;
    const int tig = lane & 3;

    const uint32_t a_off = (uint32_t)(warp_m * 32 + (lane & 7) + ((lane >> 3) & 1) * 8) * TSTRIDE
                         + (uint32_t)(lane >> 4) * 16;
    const uint32_t b_off = (uint32_t)(warp_n * 64 + (lane & 7) + (lane >> 4) * 8) * TSTRIDE
                         + (uint32_t)((lane >> 3) & 1) * 16;
    const uint32_t a_hi = sbase + AH_OFF + a_off;
    const uint32_t a_lo = sbase + AL_OFF + a_off;
    const uint32_t b_hi = sbase + BH_OFF + b_off;
    const uint32_t b_lo = sbase + BL_OFF + b_off;

    float acc[2][8][4];
    #pragma unroll
    for (int i = 0; i < 2; i++)
        #pragma unroll
        for (int j = 0; j < 8; j++)
            #pragma unroll
            for (int q = 0; q < 4; q++) acc[i][j][q] = 0.f;

    #pragma unroll
    for (int kc = 0; kc < 8; kc++) {
        const uint32_t kb = (uint32_t)kc * 32;
        uint32_t ah0[4], ah1[4], al0[4], al1[4];
        ldsm4(ah0, a_hi + kb);
        ldsm4(ah1, a_hi + 16 * TSTRIDE + kb);
        ldsm4(al0, a_lo + kb);
        ldsm4(al1, a_lo + 16 * TSTRIDE + kb);
        #pragma unroll
        for (int g = 0; g < 4; g++) {
            uint32_t bh[4], bl[4];
            ldsm4(bh, b_hi + (uint32_t)g * 16 * TSTRIDE + kb);
            ldsm4(bl, b_lo + (uint32_t)g * 16 * TSTRIDE + kb);
            const int n0 = 2 * g, n1 = 2 * g + 1;
            mma16816(acc[0][n0], ah0, bh[0], bh[1]);
            mma16816(acc[0][n1], ah0, bh[2], bh[3]);
            mma16816(acc[1][n0], ah1, bh[0], bh[1]);
            mma16816(acc[1][n1], ah1, bh[2], bh[3]);
            mma16816(acc[0][n0], ah0, bl[0], bl[1]);
            mma16816(acc[0][n1], ah0, bl[2], bl[3]);
            mma16816(acc[1][n0], ah1, bl[0], bl[1]);
            mma16816(acc[1][n1], ah1, bl[2], bl[3]);
            mma16816(acc[0][n0], al0, bh[0], bh[1]);
            mma16816(acc[0][n1], al0, bh[2], bh[3]);
            mma16816(acc[1][n0], al1, bh[0], bh[1]);
            mma16816(acc[1][n1], al1, bh[2], bh[3]);
        }
    }

    const float* sbias = (const float*)smem;
    #pragma unroll
    for (int mt = 0; mt < 2; mt++) {
        #pragma unroll
        for (int h = 0; h < 2; h++) {
            const int rloc = warp_m * 32 + mt * 16 + h * 8 + gid;
            if (rloc >= rvalid) continue;
            const int r = row0 + rloc;
            float sc = 0.f;
            if (MODE == 1) { const float iv = g_inv[r]; sc = iv * iv; }
            #pragma unroll
            for (int nt = 0; nt < 8; nt++) {
                const int col = warp_n * 64 + nt * 8 + 2 * tig;
                const float c0 = acc[mt][nt][h * 2 + 0];
                const float c1 = acc[mt][nt][h * 2 + 1];
                const float b0 = sbias[col], b1 = sbias[col + 1];
                if (MODE == 0) {
                    float2 v = make_float2(fmaxf(c0 + b0, 0.f), fmaxf(c1 + b1, 0.f));
                    *(float2*)(out + (size_t)r * DIM + col) = v;
                } else {
                    *(float2*)(out + (size_t)r * DIM + col) = make_float2(c0, c1);
                    float2 gg = make_float2(fmaf(c0, sc, b0), fmaf(c1, sc, b1));
                    *(float2*)(agg + (size_t)r * DIM + col) = gg;
                }
            }
        }
    }
}

// ==================== gather aggregation (no atomics) ========================
// One warp per node: agg[n] += inv[n] * sum_{e in CSR[n]} inv[src]*hw[src]
__global__ __launch_bounds__(256)
void gather_kernel(const float* __restrict__ hw, float* __restrict__ agg)
{
    const int node = (blockIdx.x * blockDim.x + threadIdx.x) >> 5;
    const int lane = threadIdx.x & 31;
    if (node >= NNODES) return;
    const int e0 = g_off[node];
    const int e1 = g_off[node + 1];

    float4 acc = make_float4(0.f, 0.f, 0.f, 0.f);
    int e = e0;
    for (; e + 2 <= e1; e += 2) {
        const int2 sw0 = g_csr[e];
        const int2 sw1 = g_csr[e + 1];
        const float4 v0 = ((const float4*)(hw + (size_t)sw0.x * DIM))[lane];
        const float4 v1 = ((const float4*)(hw + (size_t)sw1.x * DIM))[lane];
        const float w0 = __int_as_float(sw0.y);
        const float w1 = __int_as_float(sw1.y);
        acc.x = fmaf(v0.x, w0, acc.x); acc.y = fmaf(v0.y, w0, acc.y);
        acc.z = fmaf(v0.z, w0, acc.z); acc.w = fmaf(v0.w, w0, acc.w);
        acc.x = fmaf(v1.x, w1, acc.x); acc.y = fmaf(v1.y, w1, acc.y);
        acc.z = fmaf(v1.z, w1, acc.z); acc.w = fmaf(v1.w, w1, acc.w);
    }
    if (e < e1) {
        const int2 sw = g_csr[e];
        const float4 v = ((const float4*)(hw + (size_t)sw.x * DIM))[lane];
        const float w = __int_as_float(sw.y);
        acc.x = fmaf(v.x, w, acc.x); acc.y = fmaf(v.y, w, acc.y);
        acc.z = fmaf(v.z, w, acc.z); acc.w = fmaf(v.w, w, acc.w);
    }

    const float invd = g_inv[node];
    float4* arow = (float4*)(agg + (size_t)node * DIM);
    float4 a = arow[lane];
    a.x = fmaf(acc.x, invd, a.x); a.y = fmaf(acc.y, invd, a.y);
    a.z = fmaf(acc.z, invd, a.z); a.w = fmaf(acc.w, invd, a.w);
    arow[lane] = a;
}

// ==================== pool: segment sums (batch is sorted) ===================
__global__ void gstart_kernel(const int* __restrict__ batch, int N) {
    const int g = blockIdx.x * blockDim.x + threadIdx.x;
    if (g > NGRAPH) return;
    if (g == NGRAPH) { g_gstart[NGRAPH] = N; return; }
    // lower_bound: first i with batch[i] >= g
    int lo = 0, hi = N;
    while (lo < hi) {
        int mid = (lo + hi) >> 1;
        if (batch[mid] < g) lo = mid + 1; else hi = mid;
    }
    g_gstart[g] = lo;
}

// block per graph, 128 threads: pool[g][c] = sum over rows of relu(agg)
__global__ __launch_bounds__(128)
void pool_kernel(const float* __restrict__ h)
{
    const int g = blockIdx.x;
    const int c = threadIdx.x;
    const int lo = g_gstart[g];
    const int hi = g_gstart[g + 1];
    float s = 0.f;
    for (int i = lo; i < hi; i++)
        s += fmaxf(h[(size_t)i * DIM + c], 0.f);
    g_pool[(size_t)g * DIM + c] = s;
}

__global__ void dec2_kernel(const float* __restrict__ dec1,
                            const float* __restrict__ W2,
                            const float* __restrict__ b2,
                            float* __restrict__ out)
{
    const int idx = blockIdx.x * blockDim.x + threadIdx.x;
    if (idx >= NGRAPH * OUTD) return;
    const int g = idx >> 5;
    const int o = idx & 31;
    const float* row = dec1 + (size_t)g * DIM;
    float s = b2[o];
    #pragma unroll 8
    for (int k = 0; k < DIM; k++) s = fmaf(row[k], W2[k * OUTD + o], s);
    out[idx] = s;
}

// ==================== host launch ===========================================
extern "C" void kernel_launch(void* const* d_in, const int* in_sizes, int n_in,
                              void* d_out, int out_size)
{
    const float* x       = (const float*)d_in[0];
    const int*   eidx    = (const int*)  d_in[1];
    const int*   batch   = (const int*)  d_in[2];
    const float* enc_W1  = (const float*)d_in[3];
    const float* enc_b1  = (const float*)d_in[4];
    const float* enc_W2  = (const float*)d_in[5];
    const float* enc_b2  = (const float*)d_in[6];
    const float* gcn_W   = (const float*)d_in[7];
    const float* gcn_b   = (const float*)d_in[8];
    const float* dec_W1  = (const float*)d_in[9];
    const float* dec_b1  = (const float*)d_in[10];
    const float* dec_W2  = (const float*)d_in[11];
    const float* dec_b2  = (const float*)d_in[12];

    const int N = in_sizes[0] / DIM;
    const int E = in_sizes[1] / 2;
    const int* src = eidx;
    const int* dst = eidx + E;

    float *bufp, *hwp, *aggp, *poolp, *dec1p;
    __nv_bfloat16 *whip, *wlop;
    cudaGetSymbolAddress((void**)&bufp,  g_buf);
    cudaGetSymbolAddress((void**)&hwp,   g_hw);
    cudaGetSymbolAddress((void**)&aggp,  g_agg);
    cudaGetSymbolAddress((void**)&poolp, g_pool);
    cudaGetSymbolAddress((void**)&dec1p, g_dec1);
    cudaGetSymbolAddress((void**)&whip,  g_whi);
    cudaGetSymbolAddress((void**)&wlop,  g_wlo);

    cudaFuncSetAttribute(mmagemm_kernel<0,false>,
                         cudaFuncAttributeMaxDynamicSharedMemorySize, SMEM_BYTES);
    cudaFuncSetAttribute(mmagemm_kernel<1,false>,
                         cudaFuncAttributeMaxDynamicSharedMemorySize, SMEM_BYTES);
    cudaFuncSetAttribute(mmagemm_kernel<1,true>,
                         cudaFuncAttributeMaxDynamicSharedMemorySize, SMEM_BYTES);

    const int WSZ = DIM * DIM;
    const int gemm_blocks = (N + 127) / 128;

    // 1) CSR build + normalization + weight prep
    zero_cnt_kernel<<<(NNODES + 255) / 256, 256>>>();
    hist_kernel<<<(E + 255) / 256, 256>>>(dst, E);
    invsqrt_kernel<<<(N + 255) / 256, 256>>>(N);
    scan_kernel<<<1, 1024>>>();
    bin_kernel<<<(E + 255) / 256, 256>>>(src, dst, E);
    {
        WPtrs wp;
        wp.w[0] = enc_W1; wp.w[1] = enc_W2;
        wp.w[2] = gcn_W;  wp.w[3] = gcn_W + WSZ; wp.w[4] = gcn_W + 2 * WSZ;
        wp.w[5] = dec_W1;
        prepw_kernel<<<NMAT * 64, 256>>>(wp);
    }

    // 2) encoder MLP
    mmagemm_kernel<0,false><<<gemm_blocks, 256, SMEM_BYTES>>>(
        x, whip + 0 * WSZ, wlop + 0 * WSZ, enc_b1, bufp, nullptr, N);
    mmagemm_kernel<0,false><<<gemm_blocks, 256, SMEM_BYTES>>>(
        bufp, whip + 1 * WSZ, wlop + 1 * WSZ, enc_b2, bufp, nullptr, N);

    // 3) GCN layers: GEMM (agg pre-init fused) -> CSR gather (no atomics)
    const int gather_blocks = (NNODES * 32 + 255) / 256;
    for (int l = 0; l < NLAYER; l++) {
        if (l == 0)
            mmagemm_kernel<1,false><<<gemm_blocks, 256, SMEM_BYTES>>>(
                bufp, whip + (2 + l) * WSZ, wlop + (2 + l) * WSZ,
                gcn_b + (size_t)l * DIM, hwp, aggp, N);
        else
            mmagemm_kernel<1,true><<<gemm_blocks, 256, SMEM_BYTES>>>(
                aggp, whip + (2 + l) * WSZ, wlop + (2 + l) * WSZ,
                gcn_b + (size_t)l * DIM, hwp, aggp, N);
        gather_kernel<<<gather_blocks, 256>>>(hwp, aggp);
    }

    // 4) global add pool: segment sums over sorted batch
    gstart_kernel<<<3, 256>>>(batch, N);
    pool_kernel<<<NGRAPH, 128>>>(aggp);

    // 5) decoder
    mmagemm_kernel<0,false><<<(NGRAPH + 127) / 128, 256, SMEM_BYTES>>>(
        poolp, whip + 5 * WSZ, wlop + 5 * WSZ, dec_b1, dec1p, nullptr, NGRAPH);
    dec2_kernel<<<(NGRAPH * OUTD + 255) / 256, 256>>>(dec1p, dec_W2, dec_b2, (float*)d_out);
}

// round 8
// speedup vs baseline: 2.0169x; 1.2643x over previous
#include <cuda_runtime.h>
#include <cuda_bf16.h>
#include <cstdint>

#define NNODES 100000
#define NEDGES 1600000
#define DIM    128
#define OUTD   32
#define NGRAPH 512
#define NLAYER 3
#define NMAT   6          // enc1, enc2, gcn0, gcn1, gcn2, dec1
#define NBLK   ((NNODES + 255) / 256)   // 391 scan blocks

// ---------------- scratch (static __device__ — no allocation allowed) -------
__device__ float g_buf [NNODES * DIM];
__device__ float g_hw  [NNODES * DIM];
__device__ float g_agg [NNODES * DIM];
__device__ float g_inv [NNODES];
__device__ float g_pool[NGRAPH * DIM];
__device__ float g_dec1[NGRAPH * DIM];
__device__ int   g_cnt [NNODES];
__device__ int   g_off [NNODES + 1];
__device__ int   g_cur [NNODES];
__device__ int   g_bsum[NBLK];
__device__ int   g_bpre[NBLK];
__device__ int   g_gstart[NGRAPH + 1];
__device__ int2  g_csr [NEDGES];          // {src, bits(inv[src])} binned by dst
// bf16 weight images, B-operand layout: Bimg[n][k] = W[k][n], linear [n*128+k]
__device__ __nv_bfloat16 g_whi[NMAT * DIM * DIM];
__device__ __nv_bfloat16 g_wlo[NMAT * DIM * DIM];

// ==================== helpers ===============================================
__device__ __forceinline__ uint32_t smem_u32(const void* p) {
    uint32_t a;
    asm("{ .reg .u64 t; cvta.to.shared.u64 t, %1; cvt.u32.u64 %0, t; }"
        : "=r"(a) : "l"(p));
    return a;
}

__device__ __forceinline__ void ldsm4(uint32_t* r, uint32_t addr) {
    asm volatile("ldmatrix.sync.aligned.m8n8.x4.shared.b16 {%0,%1,%2,%3}, [%4];"
                 : "=r"(r[0]), "=r"(r[1]), "=r"(r[2]), "=r"(r[3]) : "r"(addr));
}

__device__ __forceinline__ void mma16816(float* c, const uint32_t* a,
                                         uint32_t b0, uint32_t b1) {
    asm volatile(
        "mma.sync.aligned.m16n8k16.row.col.f32.bf16.bf16.f32 "
        "{%0,%1,%2,%3}, {%4,%5,%6,%7}, {%8,%9}, {%0,%1,%2,%3};"
        : "+f"(c[0]), "+f"(c[1]), "+f"(c[2]), "+f"(c[3])
        : "r"(a[0]), "r"(a[1]), "r"(a[2]), "r"(a[3]), "r"(b0), "r"(b1));
}

// ==================== weight prep: fp32 W -> bf16 hi/lo transposed images ====
struct WPtrs { const float* w[NMAT]; };

__global__ void prepw_kernel(WPtrs wp) {
    const int mat = blockIdx.x >> 6;
    const int i0  = (blockIdx.x & 63) * 256 + threadIdx.x;   // = n*128+k
    const float* W = wp.w[mat];
    const int n = i0 >> 7, k = i0 & 127;
    const float w = W[k * DIM + n];
    const __nv_bfloat16 h = __float2bfloat16_rn(w);
    const __nv_bfloat16 l = __float2bfloat16_rn(w - __bfloat162float(h));
    g_whi[mat * DIM * DIM + i0] = h;
    g_wlo[mat * DIM * DIM + i0] = l;
}

// ==================== CSR build =============================================
__global__ void zero_cnt_kernel() {
    int i = blockIdx.x * blockDim.x + threadIdx.x;
    if (i < NNODES) g_cnt[i] = 0;
}

__global__ void hist_kernel(const int* __restrict__ dst, int E) {
    int e = blockIdx.x * blockDim.x + threadIdx.x;
    if (e < E) atomicAdd(&g_cnt[dst[e]], 1);
}

__global__ void invsqrt_kernel(int n) {
    int i = blockIdx.x * blockDim.x + threadIdx.x;
    if (i < n) g_inv[i] = rsqrtf((float)g_cnt[i] + 1.0f);
}

// ---- phase 1: per-block sums of g_cnt ----
__global__ void blocksum_kernel() {
    __shared__ int ss[256];
    const int t = threadIdx.x;
    const int i = blockIdx.x * 256 + t;
    ss[t] = (i < NNODES) ? g_cnt[i] : 0;
    __syncthreads();
    #pragma unroll
    for (int d = 128; d > 0; d >>= 1) {
        if (t < d) ss[t] += ss[t + d];
        __syncthreads();
    }
    if (t == 0) g_bsum[blockIdx.x] = ss[0];
}

// ---- phase 2: scan of block sums (391 values, all-SMEM) ----
__global__ void bscan_kernel() {
    __shared__ int ss[512];
    const int t = threadIdx.x;
    const int v = (t < NBLK) ? g_bsum[t] : 0;
    ss[t] = v;
    __syncthreads();
    #pragma unroll
    for (int d = 1; d < 512; d <<= 1) {
        int u = (t >= d) ? ss[t - d] : 0;
        __syncthreads();
        ss[t] += u;
        __syncthreads();
    }
    if (t < NBLK) g_bpre[t] = ss[t] - v;        // exclusive prefix
    if (t == NBLK - 1) g_off[NNODES] = ss[t];   // total = NEDGES
}

// ---- phase 3: in-block scan + global offset -> g_off, g_cur ----
__global__ void offsets_kernel() {
    __shared__ int ss[256];
    const int t = threadIdx.x;
    const int i = blockIdx.x * 256 + t;
    const int v = (i < NNODES) ? g_cnt[i] : 0;
    ss[t] = v;
    __syncthreads();
    #pragma unroll
    for (int d = 1; d < 256; d <<= 1) {
        int u = (t >= d) ? ss[t - d] : 0;
        __syncthreads();
        ss[t] += u;
        __syncthreads();
    }
    if (i < NNODES) {
        const int excl = ss[t] - v + g_bpre[blockIdx.x];
        g_off[i] = excl;
        g_cur[i] = excl;
    }
}

__global__ void bin_kernel(const int* __restrict__ src,
                           const int* __restrict__ dst, int E) {
    int e = blockIdx.x * blockDim.x + threadIdx.x;
    if (e >= E) return;
    const int s = src[e], d = dst[e];
    const int pos = atomicAdd(&g_cur[d], 1);
    g_csr[pos] = make_int2(s, __float_as_int(g_inv[s]));
}

// ==================== mma.sync GEMM: C[128,128] tile = A @ W =================
// MODE 0: out = relu(C + b)
// MODE 1: hw = C ; agg = C*inv[r]^2 + b
// RELU_IN: relu(A) while converting to bf16
#define TSTRIDE 272                 // bytes per padded row (136 bf16)
#define TILE_B  (128 * TSTRIDE)     // 34816
#define AH_OFF  1024
#define AL_OFF  (AH_OFF + TILE_B)
#define BH_OFF  (AL_OFF + TILE_B)
#define BL_OFF  (BH_OFF + TILE_B)
#define SMEM_BYTES (BL_OFF + TILE_B)

template <int MODE, bool RELU_IN>
__global__ __launch_bounds__(256, 1)
void mmagemm_kernel(const float* __restrict__ A,
                    const __nv_bfloat16* __restrict__ Whi,
                    const __nv_bfloat16* __restrict__ Wlo,
                    const float* __restrict__ bias,
                    float* __restrict__ out,
                    float* __restrict__ agg,
                    int nrows)
{
    extern __shared__ char smem[];
    const uint32_t sbase = smem_u32(smem);
    const int tid  = threadIdx.x;
    const int wid  = tid >> 5;
    const int lane = tid & 31;
    const int row0 = blockIdx.x * 128;
    const int rvalid = min(nrows - row0, 128);

    if (tid < 128) ((float*)smem)[tid] = bias[tid];

    // stage B hi/lo
    {
        const float4* sh = (const float4*)Whi;
        const float4* sl = (const float4*)Wlo;
        #pragma unroll
        for (int it = 0; it < 8; it++) {
            const int idx = tid + 256 * it;
            const int r = idx >> 4, c = idx & 15;
            *(float4*)(smem + BH_OFF + r * TSTRIDE + c * 16) = sh[idx];
            *(float4*)(smem + BL_OFF + r * TSTRIDE + c * 16) = sl[idx];
        }
    }
    // stage A: fp32 -> bf16 hi/lo (optionally relu)
    {
        #pragma unroll
        for (int it = 0; it < 16; it++) {
            const int idx = tid + 256 * it;
            const int m = idx >> 5, c4 = idx & 31;
            float4 v = make_float4(0.f, 0.f, 0.f, 0.f);
            if (m < rvalid) v = ((const float4*)(A + (size_t)(row0 + m) * DIM))[c4];
            if (RELU_IN) {
                v.x = fmaxf(v.x, 0.f); v.y = fmaxf(v.y, 0.f);
                v.z = fmaxf(v.z, 0.f); v.w = fmaxf(v.w, 0.f);
            }
            const __nv_bfloat16 h0 = __float2bfloat16_rn(v.x);
            const __nv_bfloat16 h1 = __float2bfloat16_rn(v.y);
            const __nv_bfloat16 h2 = __float2bfloat16_rn(v.z);
            const __nv_bfloat16 h3 = __float2bfloat16_rn(v.w);
            const __nv_bfloat16 l0 = __float2bfloat16_rn(v.x - __bfloat162float(h0));
            const __nv_bfloat16 l1 = __float2bfloat16_rn(v.y - __bfloat162float(h1));
            const __nv_bfloat16 l2 = __float2bfloat16_rn(v.z - __bfloat162float(h2));
            const __nv_bfloat16 l3 = __float2bfloat16_rn(v.w - __bfloat162float(h3));
            uint2 hp, lp;
            hp.x = ((uint32_t)__bfloat16_as_ushort(h1) << 16) | __bfloat16_as_ushort(h0);
            hp.y = ((uint32_t)__bfloat16_as_ushort(h3) << 16) | __bfloat16_as_ushort(h2);
            lp.x = ((uint32_t)__bfloat16_as_ushort(l1) << 16) | __bfloat16_as_ushort(l0);
            lp.y = ((uint32_t)__bfloat16_as_ushort(l3) << 16) | __bfloat16_as_ushort(l2);
            const uint32_t off = (uint32_t)m * TSTRIDE + (uint32_t)c4 * 8;
            *(uint2*)(smem + AH_OFF + off) = hp;
            *(uint2*)(smem + AL_OFF + off) = lp;
        }
    }
    __syncthreads();

    const int warp_m = wid & 3;
    const int warp_n = wid >> 2;
    const int gid = lane >> 2;
    const int tig = lane & 3;

    const uint32_t a_off = (uint32_t)(warp_m * 32 + (lane & 7) + ((lane >> 3) & 1) * 8) * TSTRIDE
                         + (uint32_t)(lane >> 4) * 16;
    const uint32_t b_off = (uint32_t)(warp_n * 64 + (lane & 7) + (lane >> 4) * 8) * TSTRIDE
                         + (uint32_t)((lane >> 3) & 1) * 16;
    const uint32_t a_hi = sbase + AH_OFF + a_off;
    const uint32_t a_lo = sbase + AL_OFF + a_off;
    const uint32_t b_hi = sbase + BH_OFF + b_off;
    const uint32_t b_lo = sbase + BL_OFF + b_off;

    float acc[2][8][4];
    #pragma unroll
    for (int i = 0; i < 2; i++)
        #pragma unroll
        for (int j = 0; j < 8; j++)
            #pragma unroll
            for (int q = 0; q < 4; q++) acc[i][j][q] = 0.f;

    #pragma unroll
    for (int kc = 0; kc < 8; kc++) {
        const uint32_t kb = (uint32_t)kc * 32;
        uint32_t ah0[4], ah1[4], al0[4], al1[4];
        ldsm4(ah0, a_hi + kb);
        ldsm4(ah1, a_hi + 16 * TSTRIDE + kb);
        ldsm4(al0, a_lo + kb);
        ldsm4(al1, a_lo + 16 * TSTRIDE + kb);
        #pragma unroll
        for (int g = 0; g < 4; g++) {
            uint32_t bh[4], bl[4];
            ldsm4(bh, b_hi + (uint32_t)g * 16 * TSTRIDE + kb);
            ldsm4(bl, b_lo + (uint32_t)g * 16 * TSTRIDE + kb);
            const int n0 = 2 * g, n1 = 2 * g + 1;
            mma16816(acc[0][n0], ah0, bh[0], bh[1]);
            mma16816(acc[0][n1], ah0, bh[2], bh[3]);
            mma16816(acc[1][n0], ah1, bh[0], bh[1]);
            mma16816(acc[1][n1], ah1, bh[2], bh[3]);
            mma16816(acc[0][n0], ah0, bl[0], bl[1]);
            mma16816(acc[0][n1], ah0, bl[2], bl[3]);
            mma16816(acc[1][n0], ah1, bl[0], bl[1]);
            mma16816(acc[1][n1], ah1, bl[2], bl[3]);
            mma16816(acc[0][n0], al0, bh[0], bh[1]);
            mma16816(acc[0][n1], al0, bh[2], bh[3]);
            mma16816(acc[1][n0], al1, bh[0], bh[1]);
            mma16816(acc[1][n1], al1, bh[2], bh[3]);
        }
    }

    const float* sbias = (const float*)smem;
    #pragma unroll
    for (int mt = 0; mt < 2; mt++) {
        #pragma unroll
        for (int h = 0; h < 2; h++) {
            const int rloc = warp_m * 32 + mt * 16 + h * 8 + gid;
            if (rloc >= rvalid) continue;
            const int r = row0 + rloc;
            float sc = 0.f;
            if (MODE == 1) { const float iv = g_inv[r]; sc = iv * iv; }
            #pragma unroll
            for (int nt = 0; nt < 8; nt++) {
                const int col = warp_n * 64 + nt * 8 + 2 * tig;
                const float c0 = acc[mt][nt][h * 2 + 0];
                const float c1 = acc[mt][nt][h * 2 + 1];
                const float b0 = sbias[col], b1 = sbias[col + 1];
                if (MODE == 0) {
                    float2 v = make_float2(fmaxf(c0 + b0, 0.f), fmaxf(c1 + b1, 0.f));
                    *(float2*)(out + (size_t)r * DIM + col) = v;
                } else {
                    *(float2*)(out + (size_t)r * DIM + col) = make_float2(c0, c1);
                    float2 gg = make_float2(fmaf(c0, sc, b0), fmaf(c1, sc, b1));
                    *(float2*)(agg + (size_t)r * DIM + col) = gg;
                }
            }
        }
    }
}

// ==================== gather aggregation (no atomics) ========================
__global__ __launch_bounds__(256)
void gather_kernel(const float* __restrict__ hw, float* __restrict__ agg)
{
    const int node = (blockIdx.x * blockDim.x + threadIdx.x) >> 5;
    const int lane = threadIdx.x & 31;
    if (node >= NNODES) return;
    const int e0 = g_off[node];
    const int e1 = g_off[node + 1];

    float4 acc = make_float4(0.f, 0.f, 0.f, 0.f);
    int e = e0;
    for (; e + 2 <= e1; e += 2) {
        const int2 sw0 = g_csr[e];
        const int2 sw1 = g_csr[e + 1];
        const float4 v0 = ((const float4*)(hw + (size_t)sw0.x * DIM))[lane];
        const float4 v1 = ((const float4*)(hw + (size_t)sw1.x * DIM))[lane];
        const float w0 = __int_as_float(sw0.y);
        const float w1 = __int_as_float(sw1.y);
        acc.x = fmaf(v0.x, w0, acc.x); acc.y = fmaf(v0.y, w0, acc.y);
        acc.z = fmaf(v0.z, w0, acc.z); acc.w = fmaf(v0.w, w0, acc.w);
        acc.x = fmaf(v1.x, w1, acc.x); acc.y = fmaf(v1.y, w1, acc.y);
        acc.z = fmaf(v1.z, w1, acc.z); acc.w = fmaf(v1.w, w1, acc.w);
    }
    if (e < e1) {
        const int2 sw = g_csr[e];
        const float4 v = ((const float4*)(hw + (size_t)sw.x * DIM))[lane];
        const float w = __int_as_float(sw.y);
        acc.x = fmaf(v.x, w, acc.x); acc.y = fmaf(v.y, w, acc.y);
        acc.z = fmaf(v.z, w, acc.z); acc.w = fmaf(v.w, w, acc.w);
    }

    const float invd = g_inv[node];
    float4* arow = (float4*)(agg + (size_t)node * DIM);
    float4 a = arow[lane];
    a.x = fmaf(acc.x, invd, a.x); a.y = fmaf(acc.y, invd, a.y);
    a.z = fmaf(acc.z, invd, a.z); a.w = fmaf(acc.w, invd, a.w);
    arow[lane] = a;
}

// ==================== pool: segment sums (batch is sorted) ===================
__global__ void gstart_kernel(const int* __restrict__ batch, int N) {
    const int g = blockIdx.x * blockDim.x + threadIdx.x;
    if (g > NGRAPH) return;
    if (g == NGRAPH) { g_gstart[NGRAPH] = N; return; }
    int lo = 0, hi = N;
    while (lo < hi) {
        int mid = (lo + hi) >> 1;
        if (batch[mid] < g) lo = mid + 1; else hi = mid;
    }
    g_gstart[g] = lo;
}

__global__ __launch_bounds__(128)
void pool_kernel(const float* __restrict__ h)
{
    const int g = blockIdx.x;
    const int c = threadIdx.x;
    const int lo = g_gstart[g];
    const int hi = g_gstart[g + 1];
    float s = 0.f;
    for (int i = lo; i < hi; i++)
        s += fmaxf(h[(size_t)i * DIM + c], 0.f);
    g_pool[(size_t)g * DIM + c] = s;
}

__global__ void dec2_kernel(const float* __restrict__ dec1,
                            const float* __restrict__ W2,
                            const float* __restrict__ b2,
                            float* __restrict__ out)
{
    const int idx = blockIdx.x * blockDim.x + threadIdx.x;
    if (idx >= NGRAPH * OUTD) return;
    const int g = idx >> 5;
    const int o = idx & 31;
    const float* row = dec1 + (size_t)g * DIM;
    float s = b2[o];
    #pragma unroll 8
    for (int k = 0; k < DIM; k++) s = fmaf(row[k], W2[k * OUTD + o], s);
    out[idx] = s;
}

// ==================== host launch ===========================================
extern "C" void kernel_launch(void* const* d_in, const int* in_sizes, int n_in,
                              void* d_out, int out_size)
{
    const float* x       = (const float*)d_in[0];
    const int*   eidx    = (const int*)  d_in[1];
    const int*   batch   = (const int*)  d_in[2];
    const float* enc_W1  = (const float*)d_in[3];
    const float* enc_b1  = (const float*)d_in[4];
    const float* enc_W2  = (const float*)d_in[5];
    const float* enc_b2  = (const float*)d_in[6];
    const float* gcn_W   = (const float*)d_in[7];
    const float* gcn_b   = (const float*)d_in[8];
    const float* dec_W1  = (const float*)d_in[9];
    const float* dec_b1  = (const float*)d_in[10];
    const float* dec_W2  = (const float*)d_in[11];
    const float* dec_b2  = (const float*)d_in[12];

    const int N = in_sizes[0] / DIM;
    const int E = in_sizes[1] / 2;
    const int* src = eidx;
    const int* dst = eidx + E;

    float *bufp, *hwp, *aggp, *poolp, *dec1p;
    __nv_bfloat16 *whip, *wlop;
    cudaGetSymbolAddress((void**)&bufp,  g_buf);
    cudaGetSymbolAddress((void**)&hwp,   g_hw);
    cudaGetSymbolAddress((void**)&aggp,  g_agg);
    cudaGetSymbolAddress((void**)&poolp, g_pool);
    cudaGetSymbolAddress((void**)&dec1p, g_dec1);
    cudaGetSymbolAddress((void**)&whip,  g_whi);
    cudaGetSymbolAddress((void**)&wlop,  g_wlo);

    cudaFuncSetAttribute(mmagemm_kernel<0,false>,
                         cudaFuncAttributeMaxDynamicSharedMemorySize, SMEM_BYTES);
    cudaFuncSetAttribute(mmagemm_kernel<1,false>,
                         cudaFuncAttributeMaxDynamicSharedMemorySize, SMEM_BYTES);
    cudaFuncSetAttribute(mmagemm_kernel<1,true>,
                         cudaFuncAttributeMaxDynamicSharedMemorySize, SMEM_BYTES);

    const int WSZ = DIM * DIM;
    const int gemm_blocks = (N + 127) / 128;

    // 1) CSR build + normalization + weight prep
    zero_cnt_kernel<<<(NNODES + 255) / 256, 256>>>();
    hist_kernel<<<(E + 255) / 256, 256>>>(dst, E);
    invsqrt_kernel<<<(N + 255) / 256, 256>>>(N);
    blocksum_kernel<<<NBLK, 256>>>();
    bscan_kernel<<<1, 512>>>();
    offsets_kernel<<<NBLK, 256>>>();
    bin_kernel<<<(E + 255) / 256, 256>>>(src, dst, E);
    {
        WPtrs wp;
        wp.w[0] = enc_W1; wp.w[1] = enc_W2;
        wp.w[2] = gcn_W;  wp.w[3] = gcn_W + WSZ; wp.w[4] = gcn_W + 2 * WSZ;
        wp.w[5] = dec_W1;
        prepw_kernel<<<NMAT * 64, 256>>>(wp);
    }

    // 2) encoder MLP
    mmagemm_kernel<0,false><<<gemm_blocks, 256, SMEM_BYTES>>>(
        x, whip + 0 * WSZ, wlop + 0 * WSZ, enc_b1, bufp, nullptr, N);
    mmagemm_kernel<0,false><<<gemm_blocks, 256, SMEM_BYTES>>>(
        bufp, whip + 1 * WSZ, wlop + 1 * WSZ, enc_b2, bufp, nullptr, N);

    // 3) GCN layers: GEMM (agg pre-init fused) -> CSR gather (no atomics)
    const int gather_blocks = (NNODES * 32 + 255) / 256;
    for (int l = 0; l < NLAYER; l++) {
        if (l == 0)
            mmagemm_kernel<1,false><<<gemm_blocks, 256, SMEM_BYTES>>>(
                bufp, whip + (2 + l) * WSZ, wlop + (2 + l) * WSZ,
                gcn_b + (size_t)l * DIM, hwp, aggp, N);
        else
            mmagemm_kernel<1,true><<<gemm_blocks, 256, SMEM_BYTES>>>(
                aggp, whip + (2 + l) * WSZ, wlop + (2 + l) * WSZ,
                gcn_b + (size_t)l * DIM, hwp, aggp, N);
        gather_kernel<<<gather_blocks, 256>>>(hwp, aggp);
    }

    // 4) global add pool: segment sums over sorted batch
    gstart_kernel<<<3, 256>>>(batch, N);
    pool_kernel<<<NGRAPH, 128>>>(aggp);

    // 5) decoder
    mmagemm_kernel<0,false><<<(NGRAPH + 127) / 128, 256, SMEM_BYTES>>>(
        poolp, whip + 5 * WSZ, wlop + 5 * WSZ, dec_b1, dec1p, nullptr, NGRAPH);
    dec2_kernel<<<(NGRAPH * OUTD + 255) / 256, 256>>>(dec1p, dec_W2, dec_b2, (float*)d_out);
}

// round 9
// speedup vs baseline: 2.1444x; 1.0632x over previous
#include <cuda_runtime.h>
#include <cuda_bf16.h>
#include <cstdint>

#define NNODES 100000
#define NEDGES 1600000
#define DIM    128
#define OUTD   32
#define NGRAPH 512
#define NLAYER 3
#define NMAT   6          // enc1, enc2, gcn0, gcn1, gcn2, dec1
#define NBLK   ((NNODES + 255) / 256)   // 391 scan blocks

// ---------------- scratch (static __device__ — no allocation allowed) -------
__device__ float g_buf [NNODES * DIM];
__device__ float g_hw  [NNODES * DIM];
__device__ float g_agg [NNODES * DIM];
__device__ float g_inv [NNODES];
__device__ float g_pool[NGRAPH * DIM];
__device__ float g_dec1[NGRAPH * DIM];
__device__ int   g_cnt [NNODES];
__device__ int   g_off [NNODES + 1];
__device__ int   g_cur [NNODES];
__device__ int   g_bsum[NBLK];
__device__ int   g_bpre[NBLK];
__device__ int   g_gstart[NGRAPH + 1];
__device__ int2  g_csr [NEDGES];          // {src, bits(inv[src])} binned by dst
// bf16 weight images, B-operand layout: Bimg[n][k] = W[k][n], linear [n*128+k]
__device__ __nv_bfloat16 g_whi[NMAT * DIM * DIM];
__device__ __nv_bfloat16 g_wlo[NMAT * DIM * DIM];

// ==================== helpers ===============================================
__device__ __forceinline__ uint32_t smem_u32(const void* p) {
    uint32_t a;
    asm("{ .reg .u64 t; cvta.to.shared.u64 t, %1; cvt.u32.u64 %0, t; }"
        : "=r"(a) : "l"(p));
    return a;
}

__device__ __forceinline__ void ldsm4(uint32_t* r, uint32_t addr) {
    asm volatile("ldmatrix.sync.aligned.m8n8.x4.shared.b16 {%0,%1,%2,%3}, [%4];"
                 : "=r"(r[0]), "=r"(r[1]), "=r"(r[2]), "=r"(r[3]) : "r"(addr));
}

__device__ __forceinline__ void mma16816(float* c, const uint32_t* a,
                                         uint32_t b0, uint32_t b1) {
    asm volatile(
        "mma.sync.aligned.m16n8k16.row.col.f32.bf16.bf16.f32 "
        "{%0,%1,%2,%3}, {%4,%5,%6,%7}, {%8,%9}, {%0,%1,%2,%3};"
        : "+f"(c[0]), "+f"(c[1]), "+f"(c[2]), "+f"(c[3])
        : "r"(a[0]), "r"(a[1]), "r"(a[2]), "r"(a[3]), "r"(b0), "r"(b1));
}

// pack two fp32 into bf16x2 hi image + lo residual image
__device__ __forceinline__ void split2(float x, float y, uint32_t& hi, uint32_t& lo) {
    const __nv_bfloat16 hx = __float2bfloat16_rn(x);
    const __nv_bfloat16 hy = __float2bfloat16_rn(y);
    const __nv_bfloat16 lx = __float2bfloat16_rn(x - __bfloat162float(hx));
    const __nv_bfloat16 ly = __float2bfloat16_rn(y - __bfloat162float(hy));
    hi = ((uint32_t)__bfloat16_as_ushort(hy) << 16) | __bfloat16_as_ushort(hx);
    lo = ((uint32_t)__bfloat16_as_ushort(ly) << 16) | __bfloat16_as_ushort(lx);
}

// ==================== weight prep: fp32 W -> bf16 hi/lo transposed images ====
struct WPtrs { const float* w[NMAT]; };

__global__ void prepw_kernel(WPtrs wp) {
    const int mat = blockIdx.x >> 6;
    const int i0  = (blockIdx.x & 63) * 256 + threadIdx.x;   // = n*128+k
    const float* W = wp.w[mat];
    const int n = i0 >> 7, k = i0 & 127;
    const float w = W[k * DIM + n];
    const __nv_bfloat16 h = __float2bfloat16_rn(w);
    const __nv_bfloat16 l = __float2bfloat16_rn(w - __bfloat162float(h));
    g_whi[mat * DIM * DIM + i0] = h;
    g_wlo[mat * DIM * DIM + i0] = l;
}

// ==================== CSR build =============================================
__global__ void zero_cnt_kernel() {
    int i = blockIdx.x * blockDim.x + threadIdx.x;
    if (i < NNODES) g_cnt[i] = 0;
}

__global__ void hist_kernel(const int* __restrict__ dst, int E) {
    int e = blockIdx.x * blockDim.x + threadIdx.x;
    if (e < E) atomicAdd(&g_cnt[dst[e]], 1);
}

__global__ void invsqrt_kernel(int n) {
    int i = blockIdx.x * blockDim.x + threadIdx.x;
    if (i < n) g_inv[i] = rsqrtf((float)g_cnt[i] + 1.0f);
}

__global__ void blocksum_kernel() {
    __shared__ int ss[256];
    const int t = threadIdx.x;
    const int i = blockIdx.x * 256 + t;
    ss[t] = (i < NNODES) ? g_cnt[i] : 0;
    __syncthreads();
    #pragma unroll
    for (int d = 128; d > 0; d >>= 1) {
        if (t < d) ss[t] += ss[t + d];
        __syncthreads();
    }
    if (t == 0) g_bsum[blockIdx.x] = ss[0];
}

__global__ void bscan_kernel() {
    __shared__ int ss[512];
    const int t = threadIdx.x;
    const int v = (t < NBLK) ? g_bsum[t] : 0;
    ss[t] = v;
    __syncthreads();
    #pragma unroll
    for (int d = 1; d < 512; d <<= 1) {
        int u = (t >= d) ? ss[t - d] : 0;
        __syncthreads();
        ss[t] += u;
        __syncthreads();
    }
    if (t < NBLK) g_bpre[t] = ss[t] - v;
    if (t == NBLK - 1) g_off[NNODES] = ss[t];
}

__global__ void offsets_kernel() {
    __shared__ int ss[256];
    const int t = threadIdx.x;
    const int i = blockIdx.x * 256 + t;
    const int v = (i < NNODES) ? g_cnt[i] : 0;
    ss[t] = v;
    __syncthreads();
    #pragma unroll
    for (int d = 1; d < 256; d <<= 1) {
        int u = (t >= d) ? ss[t - d] : 0;
        __syncthreads();
        ss[t] += u;
        __syncthreads();
    }
    if (i < NNODES) {
        const int excl = ss[t] - v + g_bpre[blockIdx.x];
        g_off[i] = excl;
        g_cur[i] = excl;
    }
}

__global__ void bin_kernel(const int* __restrict__ src,
                           const int* __restrict__ dst, int E) {
    int e = blockIdx.x * blockDim.x + threadIdx.x;
    if (e >= E) return;
    const int s = src[e], d = dst[e];
    const int pos = atomicAdd(&g_cur[d], 1);
    g_csr[pos] = make_int2(s, __float_as_int(g_inv[s]));
}

// ==================== mma.sync GEMM: C[128,128] tile = A @ W =================
// A fragments loaded DIRECTLY global->regs (no SMEM staging); B hi/lo in SMEM.
// MODE 0: out = relu(C + b)
// MODE 1: hw = C ; agg = C*inv[r]^2 + b
// RELU_IN: relu(A) at load
#define TSTRIDE 272                 // bytes per padded B row (136 bf16)
#define TILE_B  (128 * TSTRIDE)     // 34816
#define BH_OFF  1024
#define BL_OFF  (BH_OFF + TILE_B)
#define SMEM_BYTES (BL_OFF + TILE_B)   // 70656

template <int MODE, bool RELU_IN>
__global__ __launch_bounds__(256, 2)
void mmagemm_kernel(const float* __restrict__ A,
                    const __nv_bfloat16* __restrict__ Whi,
                    const __nv_bfloat16* __restrict__ Wlo,
                    const float* __restrict__ bias,
                    float* __restrict__ out,
                    float* __restrict__ agg,
                    int nrows)
{
    extern __shared__ char smem[];
    const uint32_t sbase = smem_u32(smem);
    const int tid  = threadIdx.x;
    const int wid  = tid >> 5;
    const int lane = tid & 31;
    const int row0 = blockIdx.x * 128;
    const int rvalid = min(nrows - row0, 128);

    if (tid < 128) ((float*)smem)[tid] = bias[tid];

    // stage B hi/lo (linear global -> padded smem), 2048 float4 each
    {
        const float4* sh = (const float4*)Whi;
        const float4* sl = (const float4*)Wlo;
        #pragma unroll
        for (int it = 0; it < 8; it++) {
            const int idx = tid + 256 * it;
            const int r = idx >> 4, c = idx & 15;
            *(float4*)(smem + BH_OFF + r * TSTRIDE + c * 16) = sh[idx];
            *(float4*)(smem + BL_OFF + r * TSTRIDE + c * 16) = sl[idx];
        }
    }
    __syncthreads();

    const int warp_m = wid & 3;
    const int warp_n = wid >> 2;
    const int gid = lane >> 2;     // fragment row within 8
    const int tig = lane & 3;      // fragment col pair

    // 4 A-row pointers for this lane (clamped; invalid rows masked at epilogue)
    const int base = row0 + warp_m * 32 + gid;
    const float* rA0 = A + (size_t)min(base +  0, nrows - 1) * DIM + tig * 2;
    const float* rA1 = A + (size_t)min(base +  8, nrows - 1) * DIM + tig * 2;
    const float* rA2 = A + (size_t)min(base + 16, nrows - 1) * DIM + tig * 2;
    const float* rA3 = A + (size_t)min(base + 24, nrows - 1) * DIM + tig * 2;

    // B ldmatrix base
    const uint32_t b_off = (uint32_t)(warp_n * 64 + (lane & 7) + (lane >> 4) * 8) * TSTRIDE
                         + (uint32_t)((lane >> 3) & 1) * 16;
    const uint32_t b_hi = sbase + BH_OFF + b_off;
    const uint32_t b_lo = sbase + BL_OFF + b_off;

    float acc[2][8][4];
    #pragma unroll
    for (int i = 0; i < 2; i++)
        #pragma unroll
        for (int j = 0; j < 8; j++)
            #pragma unroll
            for (int q = 0; q < 4; q++) acc[i][j][q] = 0.f;

    #pragma unroll
    for (int kc = 0; kc < 8; kc++) {
        const int c0 = kc * 16;         // floats
        // load A fragments (float2 = one 8B sector-slice per lane, coalesced in 4-lane groups)
        float2 v[8];
        v[0] = *(const float2*)(rA0 + c0);
        v[1] = *(const float2*)(rA1 + c0);
        v[2] = *(const float2*)(rA2 + c0);
        v[3] = *(const float2*)(rA3 + c0);
        v[4] = *(const float2*)(rA0 + c0 + 8);
        v[5] = *(const float2*)(rA1 + c0 + 8);
        v[6] = *(const float2*)(rA2 + c0 + 8);
        v[7] = *(const float2*)(rA3 + c0 + 8);
        if (RELU_IN) {
            #pragma unroll
            for (int i = 0; i < 8; i++) {
                v[i].x = fmaxf(v[i].x, 0.f);
                v[i].y = fmaxf(v[i].y, 0.f);
            }
        }
        // convert to bf16 hi/lo fragments
        uint32_t ah0[4], ah1[4], al0[4], al1[4];
        split2(v[0].x, v[0].y, ah0[0], al0[0]);   // (gid,    k0-7)
        split2(v[1].x, v[1].y, ah0[1], al0[1]);   // (gid+8,  k0-7)
        split2(v[4].x, v[4].y, ah0[2], al0[2]);   // (gid,    k8-15)
        split2(v[5].x, v[5].y, ah0[3], al0[3]);   // (gid+8,  k8-15)
        split2(v[2].x, v[2].y, ah1[0], al1[0]);   // (gid+16, k0-7)
        split2(v[3].x, v[3].y, ah1[1], al1[1]);   // (gid+24, k0-7)
        split2(v[6].x, v[6].y, ah1[2], al1[2]);   // (gid+16, k8-15)
        split2(v[7].x, v[7].y, ah1[3], al1[3]);   // (gid+24, k8-15)

        const uint32_t kb = (uint32_t)kc * 32;
        #pragma unroll
        for (int g = 0; g < 4; g++) {
            uint32_t bh[4], bl[4];
            ldsm4(bh, b_hi + (uint32_t)g * 16 * TSTRIDE + kb);
            ldsm4(bl, b_lo + (uint32_t)g * 16 * TSTRIDE + kb);
            const int n0 = 2 * g, n1 = 2 * g + 1;
            mma16816(acc[0][n0], ah0, bh[0], bh[1]);
            mma16816(acc[0][n1], ah0, bh[2], bh[3]);
            mma16816(acc[1][n0], ah1, bh[0], bh[1]);
            mma16816(acc[1][n1], ah1, bh[2], bh[3]);
            mma16816(acc[0][n0], ah0, bl[0], bl[1]);
            mma16816(acc[0][n1], ah0, bl[2], bl[3]);
            mma16816(acc[1][n0], ah1, bl[0], bl[1]);
            mma16816(acc[1][n1], ah1, bl[2], bl[3]);
            mma16816(acc[0][n0], al0, bh[0], bh[1]);
            mma16816(acc[0][n1], al0, bh[2], bh[3]);
            mma16816(acc[1][n0], al1, bh[0], bh[1]);
            mma16816(acc[1][n1], al1, bh[2], bh[3]);
        }
    }

    const float* sbias = (const float*)smem;
    #pragma unroll
    for (int mt = 0; mt < 2; mt++) {
        #pragma unroll
        for (int h = 0; h < 2; h++) {
            const int rloc = warp_m * 32 + mt * 16 + h * 8 + gid;
            if (rloc >= rvalid) continue;
            const int r = row0 + rloc;
            float sc = 0.f;
            if (MODE == 1) { const float iv = g_inv[r]; sc = iv * iv; }
            #pragma unroll
            for (int nt = 0; nt < 8; nt++) {
                const int col = warp_n * 64 + nt * 8 + 2 * tig;
                const float c0 = acc[mt][nt][h * 2 + 0];
                const float c1 = acc[mt][nt][h * 2 + 1];
                const float b0 = sbias[col], b1 = sbias[col + 1];
                if (MODE == 0) {
                    float2 vv = make_float2(fmaxf(c0 + b0, 0.f), fmaxf(c1 + b1, 0.f));
                    *(float2*)(out + (size_t)r * DIM + col) = vv;
                } else {
                    *(float2*)(out + (size_t)r * DIM + col) = make_float2(c0, c1);
                    float2 gg = make_float2(fmaf(c0, sc, b0), fmaf(c1, sc, b1));
                    *(float2*)(agg + (size_t)r * DIM + col) = gg;
                }
            }
        }
    }
}

// ==================== gather aggregation (no atomics) ========================
__global__ __launch_bounds__(256)
void gather_kernel(const float* __restrict__ hw, float* __restrict__ agg)
{
    const int node = (blockIdx.x * blockDim.x + threadIdx.x) >> 5;
    const int lane = threadIdx.x & 31;
    if (node >= NNODES) return;
    const int e0 = g_off[node];
    const int e1 = g_off[node + 1];

    float4 acc = make_float4(0.f, 0.f, 0.f, 0.f);
    int e = e0;
    for (; e + 2 <= e1; e += 2) {
        const int2 sw0 = g_csr[e];
        const int2 sw1 = g_csr[e + 1];
        const float4 v0 = ((const float4*)(hw + (size_t)sw0.x * DIM))[lane];
        const float4 v1 = ((const float4*)(hw + (size_t)sw1.x * DIM))[lane];
        const float w0 = __int_as_float(sw0.y);
        const float w1 = __int_as_float(sw1.y);
        acc.x = fmaf(v0.x, w0, acc.x); acc.y = fmaf(v0.y, w0, acc.y);
        acc.z = fmaf(v0.z, w0, acc.z); acc.w = fmaf(v0.w, w0, acc.w);
        acc.x = fmaf(v1.x, w1, acc.x); acc.y = fmaf(v1.y, w1, acc.y);
        acc.z = fmaf(v1.z, w1, acc.z); acc.w = fmaf(v1.w, w1, acc.w);
    }
    if (e < e1) {
        const int2 sw = g_csr[e];
        const float4 v = ((const float4*)(hw + (size_t)sw.x * DIM))[lane];
        const float w = __int_as_float(sw.y);
        acc.x = fmaf(v.x, w, acc.x); acc.y = fmaf(v.y, w, acc.y);
        acc.z = fmaf(v.z, w, acc.z); acc.w = fmaf(v.w, w, acc.w);
    }

    const float invd = g_inv[node];
    float4* arow = (float4*)(agg + (size_t)node * DIM);
    float4 a = arow[lane];
    a.x = fmaf(acc.x, invd, a.x); a.y = fmaf(acc.y, invd, a.y);
    a.z = fmaf(acc.z, invd, a.z); a.w = fmaf(acc.w, invd, a.w);
    arow[lane] = a;
}

// ==================== pool: segment sums (batch is sorted) ===================
__global__ void gstart_kernel(const int* __restrict__ batch, int N) {
    const int g = blockIdx.x * blockDim.x + threadIdx.x;
    if (g > NGRAPH) return;
    if (g == NGRAPH) { g_gstart[NGRAPH] = N; return; }
    int lo = 0, hi = N;
    while (lo < hi) {
        int mid = (lo + hi) >> 1;
        if (batch[mid] < g) lo = mid + 1; else hi = mid;
    }
    g_gstart[g] = lo;
}

__global__ __launch_bounds__(128)
void pool_kernel(const float* __restrict__ h)
{
    const int g = blockIdx.x;
    const int c = threadIdx.x;
    const int lo = g_gstart[g];
    const int hi = g_gstart[g + 1];
    float s = 0.f;
    for (int i = lo; i < hi; i++)
        s += fmaxf(h[(size_t)i * DIM + c], 0.f);
    g_pool[(size_t)g * DIM + c] = s;
}

__global__ void dec2_kernel(const float* __restrict__ dec1,
                            const float* __restrict__ W2,
                            const float* __restrict__ b2,
                            float* __restrict__ out)
{
    const int idx = blockIdx.x * blockDim.x + threadIdx.x;
    if (idx >= NGRAPH * OUTD) return;
    const int g = idx >> 5;
    const int o = idx & 31;
    const float* row = dec1 + (size_t)g * DIM;
    float s = b2[o];
    #pragma unroll 8
    for (int k = 0; k < DIM; k++) s = fmaf(row[k], W2[k * OUTD + o], s);
    out[idx] = s;
}

// ==================== host launch ===========================================
extern "C" void kernel_launch(void* const* d_in, const int* in_sizes, int n_in,
                              void* d_out, int out_size)
{
    const float* x       = (const float*)d_in[0];
    const int*   eidx    = (const int*)  d_in[1];
    const int*   batch   = (const int*)  d_in[2];
    const float* enc_W1  = (const float*)d_in[3];
    const float* enc_b1  = (const float*)d_in[4];
    const float* enc_W2  = (const float*)d_in[5];
    const float* enc_b2  = (const float*)d_in[6];
    const float* gcn_W   = (const float*)d_in[7];
    const float* gcn_b   = (const float*)d_in[8];
    const float* dec_W1  = (const float*)d_in[9];
    const float* dec_b1  = (const float*)d_in[10];
    const float* dec_W2  = (const float*)d_in[11];
    const float* dec_b2  = (const float*)d_in[12];

    const int N = in_sizes[0] / DIM;
    const int E = in_sizes[1] / 2;
    const int* src = eidx;
    const int* dst = eidx + E;

    float *bufp, *hwp, *aggp, *poolp, *dec1p;
    __nv_bfloat16 *whip, *wlop;
    cudaGetSymbolAddress((void**)&bufp,  g_buf);
    cudaGetSymbolAddress((void**)&hwp,   g_hw);
    cudaGetSymbolAddress((void**)&aggp,  g_agg);
    cudaGetSymbolAddress((void**)&poolp, g_pool);
    cudaGetSymbolAddress((void**)&dec1p, g_dec1);
    cudaGetSymbolAddress((void**)&whip,  g_whi);
    cudaGetSymbolAddress((void**)&wlop,  g_wlo);

    cudaFuncSetAttribute(mmagemm_kernel<0,false>,
                         cudaFuncAttributeMaxDynamicSharedMemorySize, SMEM_BYTES);
    cudaFuncSetAttribute(mmagemm_kernel<1,false>,
                         cudaFuncAttributeMaxDynamicSharedMemorySize, SMEM_BYTES);
    cudaFuncSetAttribute(mmagemm_kernel<1,true>,
                         cudaFuncAttributeMaxDynamicSharedMemorySize, SMEM_BYTES);

    const int WSZ = DIM * DIM;
    const int gemm_blocks = (N + 127) / 128;

    // 1) CSR build + normalization + weight prep
    zero_cnt_kernel<<<(NNODES + 255) / 256, 256>>>();
    hist_kernel<<<(E + 255) / 256, 256>>>(dst, E);
    invsqrt_kernel<<<(N + 255) / 256, 256>>>(N);
    blocksum_kernel<<<NBLK, 256>>>();
    bscan_kernel<<<1, 512>>>();
    offsets_kernel<<<NBLK, 256>>>();
    bin_kernel<<<(E + 255) / 256, 256>>>(src, dst, E);
    {
        WPtrs wp;
        wp.w[0] = enc_W1; wp.w[1] = enc_W2;
        wp.w[2] = gcn_W;  wp.w[3] = gcn_W + WSZ; wp.w[4] = gcn_W + 2 * WSZ;
        wp.w[5] = dec_W1;
        prepw_kernel<<<NMAT * 64, 256>>>(wp);
    }

    // 2) encoder MLP
    mmagemm_kernel<0,false><<<gemm_blocks, 256, SMEM_BYTES>>>(
        x, whip + 0 * WSZ, wlop + 0 * WSZ, enc_b1, bufp, nullptr, N);
    mmagemm_kernel<0,false><<<gemm_blocks, 256, SMEM_BYTES>>>(
        bufp, whip + 1 * WSZ, wlop + 1 * WSZ, enc_b2, bufp, nullptr, N);

    // 3) GCN layers: GEMM (agg pre-init fused) -> CSR gather (no atomics)
    const int gather_blocks = (NNODES * 32 + 255) / 256;
    for (int l = 0; l < NLAYER; l++) {
        if (l == 0)
            mmagemm_kernel<1,false><<<gemm_blocks, 256, SMEM_BYTES>>>(
                bufp, whip + (2 + l) * WSZ, wlop + (2 + l) * WSZ,
                gcn_b + (size_t)l * DIM, hwp, aggp, N);
        else
            mmagemm_kernel<1,true><<<gemm_blocks, 256, SMEM_BYTES>>>(
                aggp, whip + (2 + l) * WSZ, wlop + (2 + l) * WSZ,
                gcn_b + (size_t)l * DIM, hwp, aggp, N);
        gather_kernel<<<gather_blocks, 256>>>(hwp, aggp);
    }

    // 4) global add pool: segment sums over sorted batch
    gstart_kernel<<<3, 256>>>(batch, N);
    pool_kernel<<<NGRAPH, 128>>>(aggp);

    // 5) decoder
    mmagemm_kernel<0,false><<<(NGRAPH + 127) / 128, 256, SMEM_BYTES>>>(
        poolp, whip + 5 * WSZ, wlop + 5 * WSZ, dec_b1, dec1p, nullptr, NGRAPH);
    dec2_kernel<<<(NGRAPH * OUTD + 255) / 256, 256>>>(dec1p, dec_W2, dec_b2, (float*)d_out);
}

// round 10
// speedup vs baseline: 2.1813x; 1.0172x over previous
#include <cuda_runtime.h>
#include <cuda_bf16.h>
#include <cstdint>

#define NNODES 100000
#define NEDGES 1600000
#define DIM    128
#define OUTD   32
#define NGRAPH 512
#define NLAYER 3
#define NMAT   6          // enc1, enc2, gcn0, gcn1, gcn2, dec1
#define NBLK   ((NNODES + 255) / 256)   // 391 scan blocks

// ---------------- scratch (static __device__ — no allocation allowed) -------
__device__ float g_buf [NNODES * DIM];
__device__ float g_hw  [NNODES * DIM];
__device__ float g_agg [NNODES * DIM];
__device__ float g_inv [NNODES];
__device__ float g_pool[NGRAPH * DIM];
__device__ float g_dec1[NGRAPH * DIM];
__device__ int   g_cnt [NNODES];
__device__ int   g_off [NNODES + 1];
__device__ int   g_cur [NNODES];
__device__ int   g_bsum[NBLK];
__device__ int   g_bpre[NBLK];
__device__ int   g_gstart[NGRAPH + 1];
__device__ int2  g_csr [NEDGES];          // {src, bits(inv[src])} binned by dst
// bf16 weight images, B-operand layout: Bimg[n][k] = W[k][n], linear [n*128+k]
__device__ __nv_bfloat16 g_whi[NMAT * DIM * DIM];
__device__ __nv_bfloat16 g_wlo[NMAT * DIM * DIM];

// ==================== helpers ===============================================
__device__ __forceinline__ uint32_t smem_u32(const void* p) {
    uint32_t a;
    asm("{ .reg .u64 t; cvta.to.shared.u64 t, %1; cvt.u32.u64 %0, t; }"
        : "=r"(a) : "l"(p));
    return a;
}

__device__ __forceinline__ void ldsm4(uint32_t* r, uint32_t addr) {
    asm volatile("ldmatrix.sync.aligned.m8n8.x4.shared.b16 {%0,%1,%2,%3}, [%4];"
                 : "=r"(r[0]), "=r"(r[1]), "=r"(r[2]), "=r"(r[3]) : "r"(addr));
}

__device__ __forceinline__ void mma16816(float* c, const uint32_t* a,
                                         uint32_t b0, uint32_t b1) {
    asm volatile(
        "mma.sync.aligned.m16n8k16.row.col.f32.bf16.bf16.f32 "
        "{%0,%1,%2,%3}, {%4,%5,%6,%7}, {%8,%9}, {%0,%1,%2,%3};"
        : "+f"(c[0]), "+f"(c[1]), "+f"(c[2]), "+f"(c[3])
        : "r"(a[0]), "r"(a[1]), "r"(a[2]), "r"(a[3]), "r"(b0), "r"(b1));
}

// pack two fp32 into bf16x2 hi image + lo residual image
__device__ __forceinline__ void split2(float x, float y, uint32_t& hi, uint32_t& lo) {
    const __nv_bfloat16 hx = __float2bfloat16_rn(x);
    const __nv_bfloat16 hy = __float2bfloat16_rn(y);
    const __nv_bfloat16 lx = __float2bfloat16_rn(x - __bfloat162float(hx));
    const __nv_bfloat16 ly = __float2bfloat16_rn(y - __bfloat162float(hy));
    hi = ((uint32_t)__bfloat16_as_ushort(hy) << 16) | __bfloat16_as_ushort(hx);
    lo = ((uint32_t)__bfloat16_as_ushort(ly) << 16) | __bfloat16_as_ushort(lx);
}

// ==================== weight prep: fp32 W -> bf16 hi/lo transposed images ====
struct WPtrs { const float* w[NMAT]; };

__global__ void prepw_kernel(WPtrs wp) {
    const int mat = blockIdx.x >> 6;
    const int i0  = (blockIdx.x & 63) * 256 + threadIdx.x;   // = n*128+k
    const float* W = wp.w[mat];
    const int n = i0 >> 7, k = i0 & 127;
    const float w = W[k * DIM + n];
    const __nv_bfloat16 h = __float2bfloat16_rn(w);
    const __nv_bfloat16 l = __float2bfloat16_rn(w - __bfloat162float(h));
    g_whi[mat * DIM * DIM + i0] = h;
    g_wlo[mat * DIM * DIM + i0] = l;
}

// ==================== CSR build =============================================
__global__ void hist_kernel(const int* __restrict__ dst, int E) {
    int e = blockIdx.x * blockDim.x + threadIdx.x;
    if (e < E) atomicAdd(&g_cnt[dst[e]], 1);
}

__global__ void invsqrt_kernel(int n) {
    int i = blockIdx.x * blockDim.x + threadIdx.x;
    if (i < n) g_inv[i] = rsqrtf((float)g_cnt[i] + 1.0f);
}

__global__ void blocksum_kernel() {
    __shared__ int ss[256];
    const int t = threadIdx.x;
    const int i = blockIdx.x * 256 + t;
    ss[t] = (i < NNODES) ? g_cnt[i] : 0;
    __syncthreads();
    #pragma unroll
    for (int d = 128; d > 0; d >>= 1) {
        if (t < d) ss[t] += ss[t + d];
        __syncthreads();
    }
    if (t == 0) g_bsum[blockIdx.x] = ss[0];
}

__global__ void bscan_kernel() {
    __shared__ int ss[512];
    const int t = threadIdx.x;
    const int v = (t < NBLK) ? g_bsum[t] : 0;
    ss[t] = v;
    __syncthreads();
    #pragma unroll
    for (int d = 1; d < 512; d <<= 1) {
        int u = (t >= d) ? ss[t - d] : 0;
        __syncthreads();
        ss[t] += u;
        __syncthreads();
    }
    if (t < NBLK) g_bpre[t] = ss[t] - v;
    if (t == NBLK - 1) g_off[NNODES] = ss[t];
}

__global__ void offsets_kernel() {
    __shared__ int ss[256];
    const int t = threadIdx.x;
    const int i = blockIdx.x * 256 + t;
    const int v = (i < NNODES) ? g_cnt[i] : 0;
    ss[t] = v;
    __syncthreads();
    #pragma unroll
    for (int d = 1; d < 256; d <<= 1) {
        int u = (t >= d) ? ss[t - d] : 0;
        __syncthreads();
        ss[t] += u;
        __syncthreads();
    }
    if (i < NNODES) {
        const int excl = ss[t] - v + g_bpre[blockIdx.x];
        g_off[i] = excl;
        g_cur[i] = excl;
    }
}

__global__ void bin_kernel(const int* __restrict__ src,
                           const int* __restrict__ dst, int E) {
    int e = blockIdx.x * blockDim.x + threadIdx.x;
    if (e >= E) return;
    const int s = src[e], d = dst[e];
    const int pos = atomicAdd(&g_cur[d], 1);
    g_csr[pos] = make_int2(s, __float_as_int(g_inv[s]));
}

// ==================== mma.sync GEMM: C[128,128] tile = A @ W =================
// A fragments loaded DIRECTLY global->regs; B hi/lo in SMEM.
// MODE 0: out = relu(C + b)
// MODE 1: hw = C ; agg = C*inv[r]^2 + b
// RELU_IN: relu(A) at load
#define TSTRIDE 272                 // bytes per padded B row (136 bf16)
#define TILE_B  (128 * TSTRIDE)     // 34816
#define BH_OFF  1024
#define BL_OFF  (BH_OFF + TILE_B)
#define SMEM_BYTES (BL_OFF + TILE_B)   // 70656

template <int MODE, bool RELU_IN>
__global__ __launch_bounds__(256, 2)
void mmagemm_kernel(const float* __restrict__ A,
                    const __nv_bfloat16* __restrict__ Whi,
                    const __nv_bfloat16* __restrict__ Wlo,
                    const float* __restrict__ bias,
                    float* __restrict__ out,
                    float* __restrict__ agg,
                    int nrows)
{
    extern __shared__ char smem[];
    const uint32_t sbase = smem_u32(smem);
    const int tid  = threadIdx.x;
    const int wid  = tid >> 5;
    const int lane = tid & 31;
    const int row0 = blockIdx.x * 128;
    const int rvalid = min(nrows - row0, 128);

    if (tid < 128) ((float*)smem)[tid] = bias[tid];

    // stage B hi/lo (linear global -> padded smem), 2048 float4 each
    {
        const float4* sh = (const float4*)Whi;
        const float4* sl = (const float4*)Wlo;
        #pragma unroll
        for (int it = 0; it < 8; it++) {
            const int idx = tid + 256 * it;
            const int r = idx >> 4, c = idx & 15;
            *(float4*)(smem + BH_OFF + r * TSTRIDE + c * 16) = sh[idx];
            *(float4*)(smem + BL_OFF + r * TSTRIDE + c * 16) = sl[idx];
        }
    }
    __syncthreads();

    const int warp_m = wid & 3;
    const int warp_n = wid >> 2;
    const int gid = lane >> 2;     // fragment row within 8
    const int tig = lane & 3;      // fragment col pair

    // 4 A-row pointers for this lane (clamped; invalid rows masked at epilogue)
    const int base = row0 + warp_m * 32 + gid;
    const float* rA0 = A + (size_t)min(base +  0, nrows - 1) * DIM + tig * 2;
    const float* rA1 = A + (size_t)min(base +  8, nrows - 1) * DIM + tig * 2;
    const float* rA2 = A + (size_t)min(base + 16, nrows - 1) * DIM + tig * 2;
    const float* rA3 = A + (size_t)min(base + 24, nrows - 1) * DIM + tig * 2;

    // B ldmatrix base
    const uint32_t b_off = (uint32_t)(warp_n * 64 + (lane & 7) + (lane >> 4) * 8) * TSTRIDE
                         + (uint32_t)((lane >> 3) & 1) * 16;
    const uint32_t b_hi = sbase + BH_OFF + b_off;
    const uint32_t b_lo = sbase + BL_OFF + b_off;

    float acc[2][8][4];
    #pragma unroll
    for (int i = 0; i < 2; i++)
        #pragma unroll
        for (int j = 0; j < 8; j++)
            #pragma unroll
            for (int q = 0; q < 4; q++) acc[i][j][q] = 0.f;

    #pragma unroll
    for (int kc = 0; kc < 8; kc++) {
        const int c0 = kc * 16;         // floats
        float2 v[8];
        v[0] = *(const float2*)(rA0 + c0);
        v[1] = *(const float2*)(rA1 + c0);
        v[2] = *(const float2*)(rA2 + c0);
        v[3] = *(const float2*)(rA3 + c0);
        v[4] = *(const float2*)(rA0 + c0 + 8);
        v[5] = *(const float2*)(rA1 + c0 + 8);
        v[6] = *(const float2*)(rA2 + c0 + 8);
        v[7] = *(const float2*)(rA3 + c0 + 8);
        if (RELU_IN) {
            #pragma unroll
            for (int i = 0; i < 8; i++) {
                v[i].x = fmaxf(v[i].x, 0.f);
                v[i].y = fmaxf(v[i].y, 0.f);
            }
        }
        uint32_t ah0[4], ah1[4], al0[4], al1[4];
        split2(v[0].x, v[0].y, ah0[0], al0[0]);   // (gid,    k0-7)
        split2(v[1].x, v[1].y, ah0[1], al0[1]);   // (gid+8,  k0-7)
        split2(v[4].x, v[4].y, ah0[2], al0[2]);   // (gid,    k8-15)
        split2(v[5].x, v[5].y, ah0[3], al0[3]);   // (gid+8,  k8-15)
        split2(v[2].x, v[2].y, ah1[0], al1[0]);   // (gid+16, k0-7)
        split2(v[3].x, v[3].y, ah1[1], al1[1]);   // (gid+24, k0-7)
        split2(v[6].x, v[6].y, ah1[2], al1[2]);   // (gid+16, k8-15)
        split2(v[7].x, v[7].y, ah1[3], al1[3]);   // (gid+24, k8-15)

        const uint32_t kb = (uint32_t)kc * 32;
        #pragma unroll
        for (int g = 0; g < 4; g++) {
            uint32_t bh[4], bl[4];
            ldsm4(bh, b_hi + (uint32_t)g * 16 * TSTRIDE + kb);
            ldsm4(bl, b_lo + (uint32_t)g * 16 * TSTRIDE + kb);
            const int n0 = 2 * g, n1 = 2 * g + 1;
            mma16816(acc[0][n0], ah0, bh[0], bh[1]);
            mma16816(acc[0][n1], ah0, bh[2], bh[3]);
            mma16816(acc[1][n0], ah1, bh[0], bh[1]);
            mma16816(acc[1][n1], ah1, bh[2], bh[3]);
            mma16816(acc[0][n0], ah0, bl[0], bl[1]);
            mma16816(acc[0][n1], ah0, bl[2], bl[3]);
            mma16816(acc[1][n0], ah1, bl[0], bl[1]);
            mma16816(acc[1][n1], ah1, bl[2], bl[3]);
            mma16816(acc[0][n0], al0, bh[0], bh[1]);
            mma16816(acc[0][n1], al0, bh[2], bh[3]);
            mma16816(acc[1][n0], al1, bh[0], bh[1]);
            mma16816(acc[1][n1], al1, bh[2], bh[3]);
        }
    }

    // RACE FIX: for in-place launches (A aliases out/agg) every warp must finish
    // reading its A fragments before any warp's epilogue stores overwrite them.
    // All conflicting accesses are within this block's 128-row tile.
    __syncthreads();

    const float* sbias = (const float*)smem;
    #pragma unroll
    for (int mt = 0; mt < 2; mt++) {
        #pragma unroll
        for (int h = 0; h < 2; h++) {
            const int rloc = warp_m * 32 + mt * 16 + h * 8 + gid;
            if (rloc >= rvalid) continue;
            const int r = row0 + rloc;
            float sc = 0.f;
            if (MODE == 1) { const float iv = g_inv[r]; sc = iv * iv; }
            #pragma unroll
            for (int nt = 0; nt < 8; nt++) {
                const int col = warp_n * 64 + nt * 8 + 2 * tig;
                const float c0 = acc[mt][nt][h * 2 + 0];
                const float c1 = acc[mt][nt][h * 2 + 1];
                const float b0 = sbias[col], b1 = sbias[col + 1];
                if (MODE == 0) {
                    float2 vv = make_float2(fmaxf(c0 + b0, 0.f), fmaxf(c1 + b1, 0.f));
                    *(float2*)(out + (size_t)r * DIM + col) = vv;
                } else {
                    *(float2*)(out + (size_t)r * DIM + col) = make_float2(c0, c1);
                    float2 gg = make_float2(fmaf(c0, sc, b0), fmaf(c1, sc, b1));
                    *(float2*)(agg + (size_t)r * DIM + col) = gg;
                }
            }
        }
    }
}

// ==================== gather aggregation (no atomics) ========================
__global__ __launch_bounds__(256)
void gather_kernel(const float* __restrict__ hw, float* __restrict__ agg)
{
    const int node = (blockIdx.x * blockDim.x + threadIdx.x) >> 5;
    const int lane = threadIdx.x & 31;
    if (node >= NNODES) return;
    const int e0 = g_off[node];
    const int e1 = g_off[node + 1];

    float4 acc = make_float4(0.f, 0.f, 0.f, 0.f);
    int e = e0;
    for (; e + 2 <= e1; e += 2) {
        const int2 sw0 = g_csr[e];
        const int2 sw1 = g_csr[e + 1];
        const float4 v0 = ((const float4*)(hw + (size_t)sw0.x * DIM))[lane];
        const float4 v1 = ((const float4*)(hw + (size_t)sw1.x * DIM))[lane];
        const float w0 = __int_as_float(sw0.y);
        const float w1 = __int_as_float(sw1.y);
        acc.x = fmaf(v0.x, w0, acc.x); acc.y = fmaf(v0.y, w0, acc.y);
        acc.z = fmaf(v0.z, w0, acc.z); acc.w = fmaf(v0.w, w0, acc.w);
        acc.x = fmaf(v1.x, w1, acc.x); acc.y = fmaf(v1.y, w1, acc.y);
        acc.z = fmaf(v1.z, w1, acc.z); acc.w = fmaf(v1.w, w1, acc.w);
    }
    if (e < e1) {
        const int2 sw = g_csr[e];
        const float4 v = ((const float4*)(hw + (size_t)sw.x * DIM))[lane];
        const float w = __int_as_float(sw.y);
        acc.x = fmaf(v.x, w, acc.x); acc.y = fmaf(v.y, w, acc.y);
        acc.z = fmaf(v.z, w, acc.z); acc.w = fmaf(v.w, w, acc.w);
    }

    const float invd = g_inv[node];
    float4* arow = (float4*)(agg + (size_t)node * DIM);
    float4 a = arow[lane];
    a.x = fmaf(acc.x, invd, a.x); a.y = fmaf(acc.y, invd, a.y);
    a.z = fmaf(acc.z, invd, a.z); a.w = fmaf(acc.w, invd, a.w);
    arow[lane] = a;
}

// ==================== pool: segment sums (batch is sorted) ===================
__global__ void gstart_kernel(const int* __restrict__ batch, int N) {
    const int g = blockIdx.x * blockDim.x + threadIdx.x;
    if (g > NGRAPH) return;
    if (g == NGRAPH) { g_gstart[NGRAPH] = N; return; }
    int lo = 0, hi = N;
    while (lo < hi) {
        int mid = (lo + hi) >> 1;
        if (batch[mid] < g) lo = mid + 1; else hi = mid;
    }
    g_gstart[g] = lo;
}

__global__ __launch_bounds__(128)
void pool_kernel(const float* __restrict__ h)
{
    const int g = blockIdx.x;
    const int c = threadIdx.x;
    const int lo = g_gstart[g];
    const int hi = g_gstart[g + 1];
    float s = 0.f;
    for (int i = lo; i < hi; i++)
        s += fmaxf(h[(size_t)i * DIM + c], 0.f);
    g_pool[(size_t)g * DIM + c] = s;
}

__global__ void dec2_kernel(const float* __restrict__ dec1,
                            const float* __restrict__ W2,
                            const float* __restrict__ b2,
                            float* __restrict__ out)
{
    const int idx = blockIdx.x * blockDim.x + threadIdx.x;
    if (idx >= NGRAPH * OUTD) return;
    const int g = idx >> 5;
    const int o = idx & 31;
    const float* row = dec1 + (size_t)g * DIM;
    float s = b2[o];
    #pragma unroll 8
    for (int k = 0; k < DIM; k++) s = fmaf(row[k], W2[k * OUTD + o], s);
    out[idx] = s;
}

// ==================== host launch ===========================================
extern "C" void kernel_launch(void* const* d_in, const int* in_sizes, int n_in,
                              void* d_out, int out_size)
{
    const float* x       = (const float*)d_in[0];
    const int*   eidx    = (const int*)  d_in[1];
    const int*   batch   = (const int*)  d_in[2];
    const float* enc_W1  = (const float*)d_in[3];
    const float* enc_b1  = (const float*)d_in[4];
    const float* enc_W2  = (const float*)d_in[5];
    const float* enc_b2  = (const float*)d_in[6];
    const float* gcn_W   = (const float*)d_in[7];
    const float* gcn_b   = (const float*)d_in[8];
    const float* dec_W1  = (const float*)d_in[9];
    const float* dec_b1  = (const float*)d_in[10];
    const float* dec_W2  = (const float*)d_in[11];
    const float* dec_b2  = (const float*)d_in[12];

    const int N = in_sizes[0] / DIM;
    const int E = in_sizes[1] / 2;
    const int* src = eidx;
    const int* dst = eidx + E;

    float *bufp, *hwp, *aggp, *poolp, *dec1p;
    int* cntp;
    __nv_bfloat16 *whip, *wlop;
    cudaGetSymbolAddress((void**)&bufp,  g_buf);
    cudaGetSymbolAddress((void**)&hwp,   g_hw);
    cudaGetSymbolAddress((void**)&aggp,  g_agg);
    cudaGetSymbolAddress((void**)&poolp, g_pool);
    cudaGetSymbolAddress((void**)&dec1p, g_dec1);
    cudaGetSymbolAddress((void**)&cntp,  g_cnt);
    cudaGetSymbolAddress((void**)&whip,  g_whi);
    cudaGetSymbolAddress((void**)&wlop,  g_wlo);

    cudaFuncSetAttribute(mmagemm_kernel<0,false>,
                         cudaFuncAttributeMaxDynamicSharedMemorySize, SMEM_BYTES);
    cudaFuncSetAttribute(mmagemm_kernel<1,false>,
                         cudaFuncAttributeMaxDynamicSharedMemorySize, SMEM_BYTES);
    cudaFuncSetAttribute(mmagemm_kernel<1,true>,
                         cudaFuncAttributeMaxDynamicSharedMemorySize, SMEM_BYTES);

    const int WSZ = DIM * DIM;
    const int gemm_blocks = (N + 127) / 128;

    // Fork a side stream off the capturing main (legacy) stream for the CSR
    // chain, which is independent of weight prep + encoder GEMMs.
    // Created fresh each call (a handful of calls total); never destroyed so
    // capture teardown stays valid.
    cudaStream_t s2;
    cudaStreamCreateWithFlags(&s2, cudaStreamNonBlocking);
    cudaEvent_t ev_fork, ev_join;
    cudaEventCreateWithFlags(&ev_fork, cudaEventDisableTiming);
    cudaEventCreateWithFlags(&ev_join, cudaEventDisableTiming);

    cudaEventRecord(ev_fork, 0);
    cudaStreamWaitEvent(s2, ev_fork, 0);

    // ---- s2: CSR build + degree normalization + pool segment starts ----
    cudaMemsetAsync(cntp, 0, NNODES * sizeof(int), s2);
    hist_kernel<<<(E + 255) / 256, 256, 0, s2>>>(dst, E);
    invsqrt_kernel<<<(N + 255) / 256, 256, 0, s2>>>(N);
    blocksum_kernel<<<NBLK, 256, 0, s2>>>();
    bscan_kernel<<<1, 512, 0, s2>>>();
    offsets_kernel<<<NBLK, 256, 0, s2>>>();
    bin_kernel<<<(E + 255) / 256, 256, 0, s2>>>(src, dst, E);
    gstart_kernel<<<3, 256, 0, s2>>>(batch, N);
    cudaEventRecord(ev_join, s2);

    // ---- main stream: weight prep + encoder MLP (independent of CSR) ----
    {
        WPtrs wp;
        wp.w[0] = enc_W1; wp.w[1] = enc_W2;
        wp.w[2] = gcn_W;  wp.w[3] = gcn_W + WSZ; wp.w[4] = gcn_W + 2 * WSZ;
        wp.w[5] = dec_W1;
        prepw_kernel<<<NMAT * 64, 256>>>(wp);
    }
    mmagemm_kernel<0,false><<<gemm_blocks, 256, SMEM_BYTES>>>(
        x, whip + 0 * WSZ, wlop + 0 * WSZ, enc_b1, bufp, nullptr, N);
    mmagemm_kernel<0,false><<<gemm_blocks, 256, SMEM_BYTES>>>(
        bufp, whip + 1 * WSZ, wlop + 1 * WSZ, enc_b2, bufp, nullptr, N);

    // join: GCN layer 0 GEMM needs g_inv; gather needs g_csr
    cudaStreamWaitEvent(0, ev_join, 0);

    // ---- GCN layers: GEMM (agg pre-init fused) -> CSR gather ----
    const int gather_blocks = (NNODES * 32 + 255) / 256;
    for (int l = 0; l < NLAYER; l++) {
        if (l == 0)
            mmagemm_kernel<1,false><<<gemm_blocks, 256, SMEM_BYTES>>>(
                bufp, whip + (2 + l) * WSZ, wlop + (2 + l) * WSZ,
                gcn_b + (size_t)l * DIM, hwp, aggp, N);
        else
            mmagemm_kernel<1,true><<<gemm_blocks, 256, SMEM_BYTES>>>(
                aggp, whip + (2 + l) * WSZ, wlop + (2 + l) * WSZ,
                gcn_b + (size_t)l * DIM, hwp, aggp, N);
        gather_kernel<<<gather_blocks, 256>>>(hwp, aggp);
    }

    // ---- global add pool + decoder ----
    pool_kernel<<<NGRAPH, 128>>>(aggp);
    mmagemm_kernel<0,false><<<(NGRAPH + 127) / 128, 256, SMEM_BYTES>>>(
        poolp, whip + 5 * WSZ, wlop + 5 * WSZ, dec_b1, dec1p, nullptr, NGRAPH);
    dec2_kernel<<<(NGRAPH * OUTD + 255) / 256, 256>>>(dec1p, dec_W2, dec_b2, (float*)d_out);
}

// round 11
// speedup vs baseline: 2.5562x; 1.1719x over previous
#include <cuda_runtime.h>
#include <cuda_bf16.h>
#include <cuda_fp16.h>
#include <cstdint>

#define NNODES 100000
#define NEDGES 1600000
#define DIM    128
#define OUTD   32
#define NGRAPH 512
#define NLAYER 3
#define NMAT   6          // enc1, enc2, gcn0, gcn1, gcn2, dec1
#define NBLK   ((NNODES + 255) / 256)   // 391 scan blocks

// ---------------- scratch (static __device__ — no allocation allowed) -------
__device__ float  g_buf [NNODES * DIM];
__device__ __half g_hwh [NNODES * DIM];   // fp16 hw (edge-gather payload)
__device__ float  g_agg [NNODES * DIM];
__device__ float  g_inv [NNODES];
__device__ float  g_pool[NGRAPH * DIM];
__device__ float  g_dec1[NGRAPH * DIM];
__device__ int    g_cnt [NNODES];
__device__ int    g_off [NNODES + 1];
__device__ int    g_cur [NNODES];
__device__ int    g_bsum[NBLK];
__device__ int    g_bpre[NBLK];
__device__ int    g_gstart[NGRAPH + 1];
__device__ int2   g_csr [NEDGES];          // {src, bits(inv[src])} binned by dst
// bf16 weight images, B-operand layout: Bimg[n][k] = W[k][n], linear [n*128+k]
__device__ __nv_bfloat16 g_whi[NMAT * DIM * DIM];
__device__ __nv_bfloat16 g_wlo[NMAT * DIM * DIM];

// ==================== helpers ===============================================
__device__ __forceinline__ uint32_t smem_u32(const void* p) {
    uint32_t a;
    asm("{ .reg .u64 t; cvta.to.shared.u64 t, %1; cvt.u32.u64 %0, t; }"
        : "=r"(a) : "l"(p));
    return a;
}

__device__ __forceinline__ void ldsm4(uint32_t* r, uint32_t addr) {
    asm volatile("ldmatrix.sync.aligned.m8n8.x4.shared.b16 {%0,%1,%2,%3}, [%4];"
                 : "=r"(r[0]), "=r"(r[1]), "=r"(r[2]), "=r"(r[3]) : "r"(addr));
}

__device__ __forceinline__ void mma16816(float* c, const uint32_t* a,
                                         uint32_t b0, uint32_t b1) {
    asm volatile(
        "mma.sync.aligned.m16n8k16.row.col.f32.bf16.bf16.f32 "
        "{%0,%1,%2,%3}, {%4,%5,%6,%7}, {%8,%9}, {%0,%1,%2,%3};"
        : "+f"(c[0]), "+f"(c[1]), "+f"(c[2]), "+f"(c[3])
        : "r"(a[0]), "r"(a[1]), "r"(a[2]), "r"(a[3]), "r"(b0), "r"(b1));
}

// pack two fp32 into bf16x2 hi image + lo residual image
__device__ __forceinline__ void split2(float x, float y, uint32_t& hi, uint32_t& lo) {
    const __nv_bfloat16 hx = __float2bfloat16_rn(x);
    const __nv_bfloat16 hy = __float2bfloat16_rn(y);
    const __nv_bfloat16 lx = __float2bfloat16_rn(x - __bfloat162float(hx));
    const __nv_bfloat16 ly = __float2bfloat16_rn(y - __bfloat162float(hy));
    hi = ((uint32_t)__bfloat16_as_ushort(hy) << 16) | __bfloat16_as_ushort(hx);
    lo = ((uint32_t)__bfloat16_as_ushort(ly) << 16) | __bfloat16_as_ushort(lx);
}

// ==================== weight prep: fp32 W -> bf16 hi/lo transposed images ====
struct WPtrs { const float* w[NMAT]; };

__global__ void prepw_kernel(WPtrs wp) {
    const int mat = blockIdx.x >> 6;
    const int i0  = (blockIdx.x & 63) * 256 + threadIdx.x;   // = n*128+k
    const float* W = wp.w[mat];
    const int n = i0 >> 7, k = i0 & 127;
    const float w = W[k * DIM + n];
    const __nv_bfloat16 h = __float2bfloat16_rn(w);
    const __nv_bfloat16 l = __float2bfloat16_rn(w - __bfloat162float(h));
    g_whi[mat * DIM * DIM + i0] = h;
    g_wlo[mat * DIM * DIM + i0] = l;
}

// ==================== CSR build =============================================
__global__ void hist_kernel(const int* __restrict__ dst, int E) {
    int e = blockIdx.x * blockDim.x + threadIdx.x;
    if (e < E) atomicAdd(&g_cnt[dst[e]], 1);
}

__global__ void invsqrt_kernel(int n) {
    int i = blockIdx.x * blockDim.x + threadIdx.x;
    if (i < n) g_inv[i] = rsqrtf((float)g_cnt[i] + 1.0f);
}

__global__ void blocksum_kernel() {
    __shared__ int ss[256];
    const int t = threadIdx.x;
    const int i = blockIdx.x * 256 + t;
    ss[t] = (i < NNODES) ? g_cnt[i] : 0;
    __syncthreads();
    #pragma unroll
    for (int d = 128; d > 0; d >>= 1) {
        if (t < d) ss[t] += ss[t + d];
        __syncthreads();
    }
    if (t == 0) g_bsum[blockIdx.x] = ss[0];
}

__global__ void bscan_kernel() {
    __shared__ int ss[512];
    const int t = threadIdx.x;
    const int v = (t < NBLK) ? g_bsum[t] : 0;
    ss[t] = v;
    __syncthreads();
    #pragma unroll
    for (int d = 1; d < 512; d <<= 1) {
        int u = (t >= d) ? ss[t - d] : 0;
        __syncthreads();
        ss[t] += u;
        __syncthreads();
    }
    if (t < NBLK) g_bpre[t] = ss[t] - v;
    if (t == NBLK - 1) g_off[NNODES] = ss[t];
}

__global__ void offsets_kernel() {
    __shared__ int ss[256];
    const int t = threadIdx.x;
    const int i = blockIdx.x * 256 + t;
    const int v = (i < NNODES) ? g_cnt[i] : 0;
    ss[t] = v;
    __syncthreads();
    #pragma unroll
    for (int d = 1; d < 256; d <<= 1) {
        int u = (t >= d) ? ss[t - d] : 0;
        __syncthreads();
        ss[t] += u;
        __syncthreads();
    }
    if (i < NNODES) {
        const int excl = ss[t] - v + g_bpre[blockIdx.x];
        g_off[i] = excl;
        g_cur[i] = excl;
    }
}

__global__ void bin_kernel(const int* __restrict__ src,
                           const int* __restrict__ dst, int E) {
    int e = blockIdx.x * blockDim.x + threadIdx.x;
    if (e >= E) return;
    const int s = src[e], d = dst[e];
    const int pos = atomicAdd(&g_cur[d], 1);
    g_csr[pos] = make_int2(s, __float_as_int(g_inv[s]));
}

// ==================== mma.sync GEMM: C[128,128] tile = A @ W =================
// A fragments loaded DIRECTLY global->regs; B hi/lo in SMEM.
// MODE 0: out(fp32) = relu(C + b)
// MODE 1: hwh(fp16) = C ; agg(fp32) = C*inv[r]^2 + b
// RELU_IN: relu(A) at load
#define TSTRIDE 272                 // bytes per padded B row (136 bf16)
#define TILE_B  (128 * TSTRIDE)     // 34816
#define BH_OFF  1024
#define BL_OFF  (BH_OFF + TILE_B)
#define SMEM_BYTES (BL_OFF + TILE_B)   // 70656

template <int MODE, bool RELU_IN>
__global__ __launch_bounds__(256, 2)
void mmagemm_kernel(const float* __restrict__ A,
                    const __nv_bfloat16* __restrict__ Whi,
                    const __nv_bfloat16* __restrict__ Wlo,
                    const float* __restrict__ bias,
                    float* __restrict__ out,
                    __half* __restrict__ hwh,
                    float* __restrict__ agg,
                    int nrows)
{
    extern __shared__ char smem[];
    const uint32_t sbase = smem_u32(smem);
    const int tid  = threadIdx.x;
    const int wid  = tid >> 5;
    const int lane = tid & 31;
    const int row0 = blockIdx.x * 128;
    const int rvalid = min(nrows - row0, 128);

    if (tid < 128) ((float*)smem)[tid] = bias[tid];

    // stage B hi/lo (linear global -> padded smem), 2048 float4 each
    {
        const float4* sh = (const float4*)Whi;
        const float4* sl = (const float4*)Wlo;
        #pragma unroll
        for (int it = 0; it < 8; it++) {
            const int idx = tid + 256 * it;
            const int r = idx >> 4, c = idx & 15;
            *(float4*)(smem + BH_OFF + r * TSTRIDE + c * 16) = sh[idx];
            *(float4*)(smem + BL_OFF + r * TSTRIDE + c * 16) = sl[idx];
        }
    }
    __syncthreads();

    const int warp_m = wid & 3;
    const int warp_n = wid >> 2;
    const int gid = lane >> 2;     // fragment row within 8
    const int tig = lane & 3;      // fragment col pair

    // 4 A-row pointers for this lane (clamped; invalid rows masked at epilogue)
    const int base = row0 + warp_m * 32 + gid;
    const float* rA0 = A + (size_t)min(base +  0, nrows - 1) * DIM + tig * 2;
    const float* rA1 = A + (size_t)min(base +  8, nrows - 1) * DIM + tig * 2;
    const float* rA2 = A + (size_t)min(base + 16, nrows - 1) * DIM + tig * 2;
    const float* rA3 = A + (size_t)min(base + 24, nrows - 1) * DIM + tig * 2;

    // B ldmatrix base
    const uint32_t b_off = (uint32_t)(warp_n * 64 + (lane & 7) + (lane >> 4) * 8) * TSTRIDE
                         + (uint32_t)((lane >> 3) & 1) * 16;
    const uint32_t b_hi = sbase + BH_OFF + b_off;
    const uint32_t b_lo = sbase + BL_OFF + b_off;

    float acc[2][8][4];
    #pragma unroll
    for (int i = 0; i < 2; i++)
        #pragma unroll
        for (int j = 0; j < 8; j++)
            #pragma unroll
            for (int q = 0; q < 4; q++) acc[i][j][q] = 0.f;

    #pragma unroll
    for (int kc = 0; kc < 8; kc++) {
        const int c0 = kc * 16;         // floats
        float2 v[8];
        v[0] = *(const float2*)(rA0 + c0);
        v[1] = *(const float2*)(rA1 + c0);
        v[2] = *(const float2*)(rA2 + c0);
        v[3] = *(const float2*)(rA3 + c0);
        v[4] = *(const float2*)(rA0 + c0 + 8);
        v[5] = *(const float2*)(rA1 + c0 + 8);
        v[6] = *(const float2*)(rA2 + c0 + 8);
        v[7] = *(const float2*)(rA3 + c0 + 8);
        if (RELU_IN) {
            #pragma unroll
            for (int i = 0; i < 8; i++) {
                v[i].x = fmaxf(v[i].x, 0.f);
                v[i].y = fmaxf(v[i].y, 0.f);
            }
        }
        uint32_t ah0[4], ah1[4], al0[4], al1[4];
        split2(v[0].x, v[0].y, ah0[0], al0[0]);   // (gid,    k0-7)
        split2(v[1].x, v[1].y, ah0[1], al0[1]);   // (gid+8,  k0-7)
        split2(v[4].x, v[4].y, ah0[2], al0[2]);   // (gid,    k8-15)
        split2(v[5].x, v[5].y, ah0[3], al0[3]);   // (gid+8,  k8-15)
        split2(v[2].x, v[2].y, ah1[0], al1[0]);   // (gid+16, k0-7)
        split2(v[3].x, v[3].y, ah1[1], al1[1]);   // (gid+24, k0-7)
        split2(v[6].x, v[6].y, ah1[2], al1[2]);   // (gid+16, k8-15)
        split2(v[7].x, v[7].y, ah1[3], al1[3]);   // (gid+24, k8-15)

        const uint32_t kb = (uint32_t)kc * 32;
        #pragma unroll
        for (int g = 0; g < 4; g++) {
            uint32_t bh[4], bl[4];
            ldsm4(bh, b_hi + (uint32_t)g * 16 * TSTRIDE + kb);
            ldsm4(bl, b_lo + (uint32_t)g * 16 * TSTRIDE + kb);
            const int n0 = 2 * g, n1 = 2 * g + 1;
            mma16816(acc[0][n0], ah0, bh[0], bh[1]);
            mma16816(acc[0][n1], ah0, bh[2], bh[3]);
            mma16816(acc[1][n0], ah1, bh[0], bh[1]);
            mma16816(acc[1][n1], ah1, bh[2], bh[3]);
            mma16816(acc[0][n0], ah0, bl[0], bl[1]);
            mma16816(acc[0][n1], ah0, bl[2], bl[3]);
            mma16816(acc[1][n0], ah1, bl[0], bl[1]);
            mma16816(acc[1][n1], ah1, bl[2], bl[3]);
            mma16816(acc[0][n0], al0, bh[0], bh[1]);
            mma16816(acc[0][n1], al0, bh[2], bh[3]);
            mma16816(acc[1][n0], al1, bh[0], bh[1]);
            mma16816(acc[1][n1], al1, bh[2], bh[3]);
        }
    }

    // RACE FIX: in-place launches (A aliases out/agg) — all warps must finish
    // reading A before any epilogue store overwrites this block's 128-row tile.
    __syncthreads();

    const float* sbias = (const float*)smem;
    #pragma unroll
    for (int mt = 0; mt < 2; mt++) {
        #pragma unroll
        for (int h = 0; h < 2; h++) {
            const int rloc = warp_m * 32 + mt * 16 + h * 8 + gid;
            if (rloc >= rvalid) continue;
            const int r = row0 + rloc;
            float sc = 0.f;
            if (MODE == 1) { const float iv = g_inv[r]; sc = iv * iv; }
            #pragma unroll
            for (int nt = 0; nt < 8; nt++) {
                const int col = warp_n * 64 + nt * 8 + 2 * tig;
                const float c0 = acc[mt][nt][h * 2 + 0];
                const float c1 = acc[mt][nt][h * 2 + 1];
                const float b0 = sbias[col], b1 = sbias[col + 1];
                if (MODE == 0) {
                    float2 vv = make_float2(fmaxf(c0 + b0, 0.f), fmaxf(c1 + b1, 0.f));
                    *(float2*)(out + (size_t)r * DIM + col) = vv;
                } else {
                    // hw in fp16 (feeds edge gather only; self term stays fp32)
                    *(__half2*)(hwh + (size_t)r * DIM + col) =
                        __floats2half2_rn(c0, c1);
                    float2 gg = make_float2(fmaf(c0, sc, b0), fmaf(c1, sc, b1));
                    *(float2*)(agg + (size_t)r * DIM + col) = gg;
                }
            }
        }
    }
}

// ==================== gather aggregation (fp16 rows, no atomics) =============
// One warp per node: agg[n] += inv[n] * sum_{e in CSR[n]} inv[src]*hw16[src]
__global__ __launch_bounds__(256)
void gather_kernel(const __half* __restrict__ hwh, float* __restrict__ agg)
{
    const int node = (blockIdx.x * blockDim.x + threadIdx.x) >> 5;
    const int lane = threadIdx.x & 31;
    if (node >= NNODES) return;
    const int e0 = g_off[node];
    const int e1 = g_off[node + 1];

    float4 acc = make_float4(0.f, 0.f, 0.f, 0.f);
    int e = e0;
    for (; e + 2 <= e1; e += 2) {
        const int2 sw0 = g_csr[e];
        const int2 sw1 = g_csr[e + 1];
        // 4 halves per lane = full 256B row per warp, coalesced
        const __half2* r0 = (const __half2*)(hwh + (size_t)sw0.x * DIM) + lane * 2;
        const __half2* r1 = (const __half2*)(hwh + (size_t)sw1.x * DIM) + lane * 2;
        const uint2 u0 = *(const uint2*)r0;
        const uint2 u1 = *(const uint2*)r1;
        const float w0 = __int_as_float(sw0.y);
        const float w1 = __int_as_float(sw1.y);
        float2 a0 = __half22float2(*(const __half2*)&u0.x);
        float2 b0 = __half22float2(*(const __half2*)&u0.y);
        float2 a1 = __half22float2(*(const __half2*)&u1.x);
        float2 b1 = __half22float2(*(const __half2*)&u1.y);
        acc.x = fmaf(a0.x, w0, acc.x); acc.y = fmaf(a0.y, w0, acc.y);
        acc.z = fmaf(b0.x, w0, acc.z); acc.w = fmaf(b0.y, w0, acc.w);
        acc.x = fmaf(a1.x, w1, acc.x); acc.y = fmaf(a1.y, w1, acc.y);
        acc.z = fmaf(b1.x, w1, acc.z); acc.w = fmaf(b1.y, w1, acc.w);
    }
    if (e < e1) {
        const int2 sw = g_csr[e];
        const __half2* r0 = (const __half2*)(hwh + (size_t)sw.x * DIM) + lane * 2;
        const uint2 u0 = *(const uint2*)r0;
        const float w = __int_as_float(sw.y);
        float2 a0 = __half22float2(*(const __half2*)&u0.x);
        float2 b0 = __half22float2(*(const __half2*)&u0.y);
        acc.x = fmaf(a0.x, w, acc.x); acc.y = fmaf(a0.y, w, acc.y);
        acc.z = fmaf(b0.x, w, acc.z); acc.w = fmaf(b0.y, w, acc.w);
    }

    const float invd = g_inv[node];
    // agg row: 4 floats per lane (16B), matches the 4 gathered halves
    float4* arow = (float4*)(agg + (size_t)node * DIM) + lane;
    float4 a = *arow;
    a.x = fmaf(acc.x, invd, a.x); a.y = fmaf(acc.y, invd, a.y);
    a.z = fmaf(acc.z, invd, a.z); a.w = fmaf(acc.w, invd, a.w);
    *arow = a;
}

// ==================== pool: segment sums (batch is sorted) ===================
__global__ void gstart_kernel(const int* __restrict__ batch, int N) {
    const int g = blockIdx.x * blockDim.x + threadIdx.x;
    if (g > NGRAPH) return;
    if (g == NGRAPH) { g_gstart[NGRAPH] = N; return; }
    int lo = 0, hi = N;
    while (lo < hi) {
        int mid = (lo + hi) >> 1;
        if (batch[mid] < g) lo = mid + 1; else hi = mid;
    }
    g_gstart[g] = lo;
}

__global__ __launch_bounds__(128)
void pool_kernel(const float* __restrict__ h)
{
    const int g = blockIdx.x;
    const int c = threadIdx.x;
    const int lo = g_gstart[g];
    const int hi = g_gstart[g + 1];
    float s = 0.f;
    for (int i = lo; i < hi; i++)
        s += fmaxf(h[(size_t)i * DIM + c], 0.f);
    g_pool[(size_t)g * DIM + c] = s;
}

__global__ void dec2_kernel(const float* __restrict__ dec1,
                            const float* __restrict__ W2,
                            const float* __restrict__ b2,
                            float* __restrict__ out)
{
    const int idx = blockIdx.x * blockDim.x + threadIdx.x;
    if (idx >= NGRAPH * OUTD) return;
    const int g = idx >> 5;
    const int o = idx & 31;
    const float* row = dec1 + (size_t)g * DIM;
    float s = b2[o];
    #pragma unroll 8
    for (int k = 0; k < DIM; k++) s = fmaf(row[k], W2[k * OUTD + o], s);
    out[idx] = s;
}

// ==================== host launch ===========================================
extern "C" void kernel_launch(void* const* d_in, const int* in_sizes, int n_in,
                              void* d_out, int out_size)
{
    const float* x       = (const float*)d_in[0];
    const int*   eidx    = (const int*)  d_in[1];
    const int*   batch   = (const int*)  d_in[2];
    const float* enc_W1  = (const float*)d_in[3];
    const float* enc_b1  = (const float*)d_in[4];
    const float* enc_W2  = (const float*)d_in[5];
    const float* enc_b2  = (const float*)d_in[6];
    const float* gcn_W   = (const float*)d_in[7];
    const float* gcn_b   = (const float*)d_in[8];
    const float* dec_W1  = (const float*)d_in[9];
    const float* dec_b1  = (const float*)d_in[10];
    const float* dec_W2  = (const float*)d_in[11];
    const float* dec_b2  = (const float*)d_in[12];

    const int N = in_sizes[0] / DIM;
    const int E = in_sizes[1] / 2;
    const int* src = eidx;
    const int* dst = eidx + E;

    float *bufp, *aggp, *poolp, *dec1p;
    __half* hwhp;
    int* cntp;
    __nv_bfloat16 *whip, *wlop;
    cudaGetSymbolAddress((void**)&bufp,  g_buf);
    cudaGetSymbolAddress((void**)&hwhp,  g_hwh);
    cudaGetSymbolAddress((void**)&aggp,  g_agg);
    cudaGetSymbolAddress((void**)&poolp, g_pool);
    cudaGetSymbolAddress((void**)&dec1p, g_dec1);
    cudaGetSymbolAddress((void**)&cntp,  g_cnt);
    cudaGetSymbolAddress((void**)&whip,  g_whi);
    cudaGetSymbolAddress((void**)&wlop,  g_wlo);

    cudaFuncSetAttribute(mmagemm_kernel<0,false>,
                         cudaFuncAttributeMaxDynamicSharedMemorySize, SMEM_BYTES);
    cudaFuncSetAttribute(mmagemm_kernel<1,false>,
                         cudaFuncAttributeMaxDynamicSharedMemorySize, SMEM_BYTES);
    cudaFuncSetAttribute(mmagemm_kernel<1,true>,
                         cudaFuncAttributeMaxDynamicSharedMemorySize, SMEM_BYTES);

    const int WSZ = DIM * DIM;
    const int gemm_blocks = (N + 127) / 128;

    // Fork a side stream for the CSR chain (independent of prep + encoder).
    cudaStream_t s2;
    cudaStreamCreateWithFlags(&s2, cudaStreamNonBlocking);
    cudaEvent_t ev_fork, ev_join;
    cudaEventCreateWithFlags(&ev_fork, cudaEventDisableTiming);
    cudaEventCreateWithFlags(&ev_join, cudaEventDisableTiming);

    cudaEventRecord(ev_fork, 0);
    cudaStreamWaitEvent(s2, ev_fork, 0);

    // ---- s2: CSR build + degree normalization + pool segment starts ----
    cudaMemsetAsync(cntp, 0, NNODES * sizeof(int), s2);
    hist_kernel<<<(E + 255) / 256, 256, 0, s2>>>(dst, E);
    invsqrt_kernel<<<(N + 255) / 256, 256, 0, s2>>>(N);
    blocksum_kernel<<<NBLK, 256, 0, s2>>>();
    bscan_kernel<<<1, 512, 0, s2>>>();
    offsets_kernel<<<NBLK, 256, 0, s2>>>();
    bin_kernel<<<(E + 255) / 256, 256, 0, s2>>>(src, dst, E);
    gstart_kernel<<<3, 256, 0, s2>>>(batch, N);
    cudaEventRecord(ev_join, s2);

    // ---- main stream: weight prep + encoder MLP ----
    {
        WPtrs wp;
        wp.w[0] = enc_W1; wp.w[1] = enc_W2;
        wp.w[2] = gcn_W;  wp.w[3] = gcn_W + WSZ; wp.w[4] = gcn_W + 2 * WSZ;
        wp.w[5] = dec_W1;
        prepw_kernel<<<NMAT * 64, 256>>>(wp);
    }
    mmagemm_kernel<0,false><<<gemm_blocks, 256, SMEM_BYTES>>>(
        x, whip + 0 * WSZ, wlop + 0 * WSZ, enc_b1, bufp, nullptr, nullptr, N);
    mmagemm_kernel<0,false><<<gemm_blocks, 256, SMEM_BYTES>>>(
        bufp, whip + 1 * WSZ, wlop + 1 * WSZ, enc_b2, bufp, nullptr, nullptr, N);

    // join: GCN layer 0 GEMM needs g_inv; gather needs g_csr
    cudaStreamWaitEvent(0, ev_join, 0);

    // ---- GCN layers: GEMM (agg pre-init fused) -> fp16 CSR gather ----
    const int gather_blocks = (NNODES * 32 + 255) / 256;
    for (int l = 0; l < NLAYER; l++) {
        if (l == 0)
            mmagemm_kernel<1,false><<<gemm_blocks, 256, SMEM_BYTES>>>(
                bufp, whip + (2 + l) * WSZ, wlop + (2 + l) * WSZ,
                gcn_b + (size_t)l * DIM, nullptr, hwhp, aggp, N);
        else
            mmagemm_kernel<1,true><<<gemm_blocks, 256, SMEM_BYTES>>>(
                aggp, whip + (2 + l) * WSZ, wlop + (2 + l) * WSZ,
                gcn_b + (size_t)l * DIM, nullptr, hwhp, aggp, N);
        gather_kernel<<<gather_blocks, 256>>>(hwhp, aggp);
    }

    // ---- global add pool + decoder ----
    pool_kernel<<<NGRAPH, 128>>>(aggp);
    mmagemm_kernel<0,false><<<(NGRAPH + 127) / 128, 256, SMEM_BYTES>>>(
        poolp, whip + 5 * WSZ, wlop + 5 * WSZ, dec_b1, dec1p, nullptr, nullptr, NGRAPH);
    dec2_kernel<<<(NGRAPH * OUTD + 255) / 256, 256>>>(dec1p, dec_W2, dec_b2, (float*)d_out);
}

// round 13
// speedup vs baseline: 2.8358x; 1.1094x over previous
#include <cuda_runtime.h>
#include <cuda_bf16.h>
#include <cuda_fp16.h>
#include <cstdint>

#define NNODES 100000
#define NEDGES 1600000
#define DIM    128
#define OUTD   32
#define NGRAPH 512
#define NLAYER 3
#define NMAT   6          // enc1, enc2, gcn0, gcn1, gcn2, dec1
#define NBLK   ((NNODES + 255) / 256)   // 391 scan blocks

// ---------------- scratch (static __device__ — no allocation allowed) -------
__device__ float  g_buf [NNODES * DIM];
__device__ __half g_hwh [NNODES * DIM];   // fp16 hw (gather payload + self term)
__device__ float  g_agg [NNODES * DIM];
__device__ float  g_inv [NNODES];
__device__ float  g_pool[NGRAPH * DIM];
__device__ float  g_dec1[NGRAPH * DIM];
__device__ int    g_cnt [NNODES];
__device__ int    g_off [NNODES + 1];
__device__ int    g_cur [NNODES];
__device__ int    g_bsum[NBLK];
__device__ int    g_bpre[NBLK];
__device__ int    g_gstart[NGRAPH + 1];
__device__ int2   g_csr [NEDGES];          // {src, bits(inv[src])} binned by dst
// bf16 weight images, B-operand layout: Bimg[n][k] = W[k][n], linear [n*128+k]
__device__ __nv_bfloat16 g_whi[NMAT * DIM * DIM];
__device__ __nv_bfloat16 g_wlo[NMAT * DIM * DIM];

// ==================== helpers ===============================================
__device__ __forceinline__ uint32_t smem_u32(const void* p) {
    uint32_t a;
    asm("{ .reg .u64 t; cvta.to.shared.u64 t, %1; cvt.u32.u64 %0, t; }"
        : "=r"(a) : "l"(p));
    return a;
}

__device__ __forceinline__ void ldsm4(uint32_t* r, uint32_t addr) {
    asm volatile("ldmatrix.sync.aligned.m8n8.x4.shared.b16 {%0,%1,%2,%3}, [%4];"
                 : "=r"(r[0]), "=r"(r[1]), "=r"(r[2]), "=r"(r[3]) : "r"(addr));
}

__device__ __forceinline__ void mma16816(float* c, const uint32_t* a,
                                         uint32_t b0, uint32_t b1) {
    asm volatile(
        "mma.sync.aligned.m16n8k16.row.col.f32.bf16.bf16.f32 "
        "{%0,%1,%2,%3}, {%4,%5,%6,%7}, {%8,%9}, {%0,%1,%2,%3};"
        : "+f"(c[0]), "+f"(c[1]), "+f"(c[2]), "+f"(c[3])
        : "r"(a[0]), "r"(a[1]), "r"(a[2]), "r"(a[3]), "r"(b0), "r"(b1));
}

// pack two fp32 into bf16x2 hi image + lo residual image
__device__ __forceinline__ void split2(float x, float y, uint32_t& hi, uint32_t& lo) {
    const __nv_bfloat16 hx = __float2bfloat16_rn(x);
    const __nv_bfloat16 hy = __float2bfloat16_rn(y);
    const __nv_bfloat16 lx = __float2bfloat16_rn(x - __bfloat162float(hx));
    const __nv_bfloat16 ly = __float2bfloat16_rn(y - __bfloat162float(hy));
    hi = ((uint32_t)__bfloat16_as_ushort(hy) << 16) | __bfloat16_as_ushort(hx);
    lo = ((uint32_t)__bfloat16_as_ushort(ly) << 16) | __bfloat16_as_ushort(lx);
}

// ==================== weight prep: fp32 W -> bf16 hi/lo transposed images ====
struct WPtrs { const float* w[NMAT]; };

__global__ void prepw_kernel(WPtrs wp) {
    const int mat = blockIdx.x >> 6;
    const int i0  = (blockIdx.x & 63) * 256 + threadIdx.x;   // = n*128+k
    const float* W = wp.w[mat];
    const int n = i0 >> 7, k = i0 & 127;
    const float w = W[k * DIM + n];
    const __nv_bfloat16 h = __float2bfloat16_rn(w);
    const __nv_bfloat16 l = __float2bfloat16_rn(w - __bfloat162float(h));
    g_whi[mat * DIM * DIM + i0] = h;
    g_wlo[mat * DIM * DIM + i0] = l;
}

// ==================== CSR build =============================================
__global__ void hist_kernel(const int* __restrict__ dst, int E) {
    int e = blockIdx.x * blockDim.x + threadIdx.x;
    if (e < E) atomicAdd(&g_cnt[dst[e]], 1);
}

__global__ void invsqrt_kernel(int n) {
    int i = blockIdx.x * blockDim.x + threadIdx.x;
    if (i < n) g_inv[i] = rsqrtf((float)g_cnt[i] + 1.0f);
}

__global__ void blocksum_kernel() {
    __shared__ int ss[256];
    const int t = threadIdx.x;
    const int i = blockIdx.x * 256 + t;
    ss[t] = (i < NNODES) ? g_cnt[i] : 0;
    __syncthreads();
    #pragma unroll
    for (int d = 128; d > 0; d >>= 1) {
        if (t < d) ss[t] += ss[t + d];
        __syncthreads();
    }
    if (t == 0) g_bsum[blockIdx.x] = ss[0];
}

__global__ void bscan_kernel() {
    __shared__ int ss[512];
    const int t = threadIdx.x;
    const int v = (t < NBLK) ? g_bsum[t] : 0;
    ss[t] = v;
    __syncthreads();
    #pragma unroll
    for (int d = 1; d < 512; d <<= 1) {
        int u = (t >= d) ? ss[t - d] : 0;
        __syncthreads();
        ss[t] += u;
        __syncthreads();
    }
    if (t < NBLK) g_bpre[t] = ss[t] - v;
    if (t == NBLK - 1) g_off[NNODES] = ss[t];
}

__global__ void offsets_kernel() {
    __shared__ int ss[256];
    const int t = threadIdx.x;
    const int i = blockIdx.x * 256 + t;
    const int v = (i < NNODES) ? g_cnt[i] : 0;
    ss[t] = v;
    __syncthreads();
    #pragma unroll
    for (int d = 1; d < 256; d <<= 1) {
        int u = (t >= d) ? ss[t - d] : 0;
        __syncthreads();
        ss[t] += u;
        __syncthreads();
    }
    if (i < NNODES) {
        const int excl = ss[t] - v + g_bpre[blockIdx.x];
        g_off[i] = excl;
        g_cur[i] = excl;
    }
}

__global__ void bin_kernel(const int* __restrict__ src,
                           const int* __restrict__ dst, int E) {
    int e = blockIdx.x * blockDim.x + threadIdx.x;
    if (e >= E) return;
    const int s = src[e], d = dst[e];
    const int pos = atomicAdd(&g_cur[d], 1);
    g_csr[pos] = make_int2(s, __float_as_int(g_inv[s]));
}

// ==================== mma.sync GEMM: C[128,128] tile = A @ W =================
// A fragments loaded DIRECTLY global->regs; B hi/lo in SMEM.
// MODE 0: out(fp32) = relu(C + b)
// MODE 1: hwh(fp16) = C            (agg init moved into gather)
// RELU_IN: relu(A) at load
#define TSTRIDE 272                 // bytes per padded B row (136 bf16)
#define TILE_B  (128 * TSTRIDE)     // 34816
#define BH_OFF  1024
#define BL_OFF  (BH_OFF + TILE_B)
#define SMEM_BYTES (BL_OFF + TILE_B)   // 70656

template <int MODE, bool RELU_IN>
__global__ __launch_bounds__(256, 2)
void mmagemm_kernel(const float* __restrict__ A,
                    const __nv_bfloat16* __restrict__ Whi,
                    const __nv_bfloat16* __restrict__ Wlo,
                    const float* __restrict__ bias,
                    float* __restrict__ out,
                    __half* __restrict__ hwh,
                    int nrows)
{
    extern __shared__ char smem[];
    const uint32_t sbase = smem_u32(smem);
    const int tid  = threadIdx.x;
    const int wid  = tid >> 5;
    const int lane = tid & 31;
    const int row0 = blockIdx.x * 128;
    const int rvalid = min(nrows - row0, 128);

    if (MODE == 0 && tid < 128) ((float*)smem)[tid] = bias[tid];

    // stage B hi/lo (linear global -> padded smem), 2048 float4 each
    {
        const float4* sh = (const float4*)Whi;
        const float4* sl = (const float4*)Wlo;
        #pragma unroll
        for (int it = 0; it < 8; it++) {
            const int idx = tid + 256 * it;
            const int r = idx >> 4, c = idx & 15;
            *(float4*)(smem + BH_OFF + r * TSTRIDE + c * 16) = sh[idx];
            *(float4*)(smem + BL_OFF + r * TSTRIDE + c * 16) = sl[idx];
        }
    }
    __syncthreads();

    const int warp_m = wid & 3;
    const int warp_n = wid >> 2;
    const int gid = lane >> 2;     // fragment row within 8
    const int tig = lane & 3;      // fragment col pair

    // 4 A-row pointers for this lane (clamped; invalid rows masked at epilogue)
    const int base = row0 + warp_m * 32 + gid;
    const float* rA0 = A + (size_t)min(base +  0, nrows - 1) * DIM + tig * 2;
    const float* rA1 = A + (size_t)min(base +  8, nrows - 1) * DIM + tig * 2;
    const float* rA2 = A + (size_t)min(base + 16, nrows - 1) * DIM + tig * 2;
    const float* rA3 = A + (size_t)min(base + 24, nrows - 1) * DIM + tig * 2;

    // B ldmatrix base
    const uint32_t b_off = (uint32_t)(warp_n * 64 + (lane & 7) + (lane >> 4) * 8) * TSTRIDE
                         + (uint32_t)((lane >> 3) & 1) * 16;
    const uint32_t b_hi = sbase + BH_OFF + b_off;
    const uint32_t b_lo = sbase + BL_OFF + b_off;

    float acc[2][8][4];
    #pragma unroll
    for (int i = 0; i < 2; i++)
        #pragma unroll
        for (int j = 0; j < 8; j++)
            #pragma unroll
            for (int q = 0; q < 4; q++) acc[i][j][q] = 0.f;

    #pragma unroll
    for (int kc = 0; kc < 8; kc++) {
        const int c0 = kc * 16;         // floats
        float2 v[8];
        v[0] = *(const float2*)(rA0 + c0);
        v[1] = *(const float2*)(rA1 + c0);
        v[2] = *(const float2*)(rA2 + c0);
        v[3] = *(const float2*)(rA3 + c0);
        v[4] = *(const float2*)(rA0 + c0 + 8);
        v[5] = *(const float2*)(rA1 + c0 + 8);
        v[6] = *(const float2*)(rA2 + c0 + 8);
        v[7] = *(const float2*)(rA3 + c0 + 8);
        if (RELU_IN) {
            #pragma unroll
            for (int i = 0; i < 8; i++) {
                v[i].x = fmaxf(v[i].x, 0.f);
                v[i].y = fmaxf(v[i].y, 0.f);
            }
        }
        uint32_t ah0[4], ah1[4], al0[4], al1[4];
        split2(v[0].x, v[0].y, ah0[0], al0[0]);   // (gid,    k0-7)
        split2(v[1].x, v[1].y, ah0[1], al0[1]);   // (gid+8,  k0-7)
        split2(v[4].x, v[4].y, ah0[2], al0[2]);   // (gid,    k8-15)
        split2(v[5].x, v[5].y, ah0[3], al0[3]);   // (gid+8,  k8-15)
        split2(v[2].x, v[2].y, ah1[0], al1[0]);   // (gid+16, k0-7)
        split2(v[3].x, v[3].y, ah1[1], al1[1]);   // (gid+24, k0-7)
        split2(v[6].x, v[6].y, ah1[2], al1[2]);   // (gid+16, k8-15)
        split2(v[7].x, v[7].y, ah1[3], al1[3]);   // (gid+24, k8-15)

        const uint32_t kb = (uint32_t)kc * 32;
        #pragma unroll
        for (int g = 0; g < 4; g++) {
            uint32_t bh[4], bl[4];
            ldsm4(bh, b_hi + (uint32_t)g * 16 * TSTRIDE + kb);
            ldsm4(bl, b_lo + (uint32_t)g * 16 * TSTRIDE + kb);
            const int n0 = 2 * g, n1 = 2 * g + 1;
            mma16816(acc[0][n0], ah0, bh[0], bh[1]);
            mma16816(acc[0][n1], ah0, bh[2], bh[3]);
            mma16816(acc[1][n0], ah1, bh[0], bh[1]);
            mma16816(acc[1][n1], ah1, bh[2], bh[3]);
            mma16816(acc[0][n0], ah0, bl[0], bl[1]);
            mma16816(acc[0][n1], ah0, bl[2], bl[3]);
            mma16816(acc[1][n0], ah1, bl[0], bl[1]);
            mma16816(acc[1][n1], ah1, bl[2], bl[3]);
            mma16816(acc[0][n0], al0, bh[0], bh[1]);
            mma16816(acc[0][n1], al0, bh[2], bh[3]);
            mma16816(acc[1][n0], al1, bh[0], bh[1]);
            mma16816(acc[1][n1], al1, bh[2], bh[3]);
        }
    }

    // RACE FIX: in-place launches (A aliases out) — all warps must finish
    // reading A before any epilogue store overwrites this block's 128-row tile.
    __syncthreads();

    const float* sbias = (const float*)smem;
    #pragma unroll
    for (int mt = 0; mt < 2; mt++) {
        #pragma unroll
        for (int h = 0; h < 2; h++) {
            const int rloc = warp_m * 32 + mt * 16 + h * 8 + gid;
            if (rloc >= rvalid) continue;
            const int r = row0 + rloc;
            #pragma unroll
            for (int nt = 0; nt < 8; nt++) {
                const int col = warp_n * 64 + nt * 8 + 2 * tig;
                const float c0 = acc[mt][nt][h * 2 + 0];
                const float c1 = acc[mt][nt][h * 2 + 1];
                if (MODE == 0) {
                    float2 vv = make_float2(fmaxf(c0 + sbias[col], 0.f),
                                            fmaxf(c1 + sbias[col + 1], 0.f));
                    *(float2*)(out + (size_t)r * DIM + col) = vv;
                } else {
                    *(__half2*)(hwh + (size_t)r * DIM + col) =
                        __floats2half2_rn(c0, c1);
                }
            }
        }
    }
}

// ==================== gather: full agg computed here (pure store) ============
// agg[n] = inv[n]*Σ_{e∈CSR[n]} inv_s*hw16[s] + inv[n]^2*hw16[n] + b
__global__ __launch_bounds__(256)
void gather_kernel(const __half* __restrict__ hwh, float* __restrict__ agg,
                   const float* __restrict__ bias)
{
    const int node = (blockIdx.x * blockDim.x + threadIdx.x) >> 5;
    const int lane = threadIdx.x & 31;
    if (node >= NNODES) return;
    const int e0 = g_off[node];
    const int e1 = g_off[node + 1];

    float4 acc = make_float4(0.f, 0.f, 0.f, 0.f);
    int e = e0;
    for (; e + 2 <= e1; e += 2) {
        const int2 sw0 = g_csr[e];
        const int2 sw1 = g_csr[e + 1];
        const uint2 u0 = *((const uint2*)(hwh + (size_t)sw0.x * DIM) + lane);
        const uint2 u1 = *((const uint2*)(hwh + (size_t)sw1.x * DIM) + lane);
        const float w0 = __int_as_float(sw0.y);
        const float w1 = __int_as_float(sw1.y);
        float2 a0 = __half22float2(*(const __half2*)&u0.x);
        float2 b0 = __half22float2(*(const __half2*)&u0.y);
        float2 a1 = __half22float2(*(const __half2*)&u1.x);
        float2 b1 = __half22float2(*(const __half2*)&u1.y);
        acc.x = fmaf(a0.x, w0, acc.x); acc.y = fmaf(a0.y, w0, acc.y);
        acc.z = fmaf(b0.x, w0, acc.z); acc.w = fmaf(b0.y, w0, acc.w);
        acc.x = fmaf(a1.x, w1, acc.x); acc.y = fmaf(a1.y, w1, acc.y);
        acc.z = fmaf(b1.x, w1, acc.z); acc.w = fmaf(b1.y, w1, acc.w);
    }
    if (e < e1) {
        const int2 sw = g_csr[e];
        const uint2 u0 = *((const uint2*)(hwh + (size_t)sw.x * DIM) + lane);
        const float w = __int_as_float(sw.y);
        float2 a0 = __half22float2(*(const __half2*)&u0.x);
        float2 b0 = __half22float2(*(const __half2*)&u0.y);
        acc.x = fmaf(a0.x, w, acc.x); acc.y = fmaf(a0.y, w, acc.y);
        acc.z = fmaf(b0.x, w, acc.z); acc.w = fmaf(b0.y, w, acc.w);
    }

    const float invd = g_inv[node];
    const float sc   = invd * invd;
    // self row (fp16) + bias
    const uint2 us = *((const uint2*)(hwh + (size_t)node * DIM) + lane);
    const float2 s0 = __half22float2(*(const __half2*)&us.x);
    const float2 s1 = __half22float2(*(const __half2*)&us.y);
    const float4 b  = *((const float4*)bias + lane);

    float4 a;
    a.x = fmaf(acc.x, invd, fmaf(s0.x, sc, b.x));
    a.y = fmaf(acc.y, invd, fmaf(s0.y, sc, b.y));
    a.z = fmaf(acc.z, invd, fmaf(s1.x, sc, b.z));
    a.w = fmaf(acc.w, invd, fmaf(s1.y, sc, b.w));
    *((float4*)(agg + (size_t)node * DIM) + lane) = a;   // pure store
}

// ==================== pool: segment sums (batch is sorted) ===================
__global__ void gstart_kernel(const int* __restrict__ batch, int N) {
    const int g = blockIdx.x * blockDim.x + threadIdx.x;
    if (g > NGRAPH) return;
    if (g == NGRAPH) { g_gstart[NGRAPH] = N; return; }
    int lo = 0, hi = N;
    while (lo < hi) {
        int mid = (lo + hi) >> 1;
        if (batch[mid] < g) lo = mid + 1; else hi = mid;
    }
    g_gstart[g] = lo;
}

__global__ __launch_bounds__(128)
void pool_kernel(const float* __restrict__ h)
{
    const int g = blockIdx.x;
    const int c = threadIdx.x;
    const int lo = g_gstart[g];
    const int hi = g_gstart[g + 1];
    float s = 0.f;
    for (int i = lo; i < hi; i++)
        s += fmaxf(h[(size_t)i * DIM + c], 0.f);
    g_pool[(size_t)g * DIM + c] = s;
}

__global__ void dec2_kernel(const float* __restrict__ dec1,
                            const float* __restrict__ W2,
                            const float* __restrict__ b2,
                            float* __restrict__ out)
{
    const int idx = blockIdx.x * blockDim.x + threadIdx.x;
    if (idx >= NGRAPH * OUTD) return;
    const int g = idx >> 5;
    const int o = idx & 31;
    const float* row = dec1 + (size_t)g * DIM;
    float s = b2[o];
    #pragma unroll 8
    for (int k = 0; k < DIM; k++) s = fmaf(row[k], W2[k * OUTD + o], s);
    out[idx] = s;
}

// ==================== host launch ===========================================
extern "C" void kernel_launch(void* const* d_in, const int* in_sizes, int n_in,
                              void* d_out, int out_size)
{
    const float* x       = (const float*)d_in[0];
    const int*   eidx    = (const int*)  d_in[1];
    const int*   batch   = (const int*)  d_in[2];
    const float* enc_W1  = (const float*)d_in[3];
    const float* enc_b1  = (const float*)d_in[4];
    const float* enc_W2  = (const float*)d_in[5];
    const float* enc_b2  = (const float*)d_in[6];
    const float* gcn_W   = (const float*)d_in[7];
    const float* gcn_b   = (const float*)d_in[8];
    const float* dec_W1  = (const float*)d_in[9];
    const float* dec_b1  = (const float*)d_in[10];
    const float* dec_W2  = (const float*)d_in[11];
    const float* dec_b2  = (const float*)d_in[12];

    const int N = in_sizes[0] / DIM;
    const int E = in_sizes[1] / 2;
    const int* src = eidx;
    const int* dst = eidx + E;

    float *bufp, *aggp, *poolp, *dec1p;
    __half* hwhp;
    int* cntp;
    __nv_bfloat16 *whip, *wlop;
    cudaGetSymbolAddress((void**)&bufp,  g_buf);
    cudaGetSymbolAddress((void**)&hwhp,  g_hwh);
    cudaGetSymbolAddress((void**)&aggp,  g_agg);
    cudaGetSymbolAddress((void**)&poolp, g_pool);
    cudaGetSymbolAddress((void**)&dec1p, g_dec1);
    cudaGetSymbolAddress((void**)&cntp,  g_cnt);
    cudaGetSymbolAddress((void**)&whip,  g_whi);
    cudaGetSymbolAddress((void**)&wlop,  g_wlo);

    cudaFuncSetAttribute(mmagemm_kernel<0,false>,
                         cudaFuncAttributeMaxDynamicSharedMemorySize, SMEM_BYTES);
    cudaFuncSetAttribute(mmagemm_kernel<1,false>,
                         cudaFuncAttributeMaxDynamicSharedMemorySize, SMEM_BYTES);
    cudaFuncSetAttribute(mmagemm_kernel<1,true>,
                         cudaFuncAttributeMaxDynamicSharedMemorySize, SMEM_BYTES);

    const int WSZ = DIM * DIM;
    const int gemm_blocks = (N + 127) / 128;

    // Fork a side stream for the CSR chain (independent of prep + encoder).
    cudaStream_t s2;
    cudaStreamCreateWithFlags(&s2, cudaStreamNonBlocking);
    cudaEvent_t ev_fork, ev_join;
    cudaEventCreateWithFlags(&ev_fork, cudaEventDisableTiming);
    cudaEventCreateWithFlags(&ev_join, cudaEventDisableTiming);

    cudaEventRecord(ev_fork, 0);
    cudaStreamWaitEvent(s2, ev_fork, 0);

    // ---- s2: CSR build + degree normalization + pool segment starts ----
    cudaMemsetAsync(cntp, 0, NNODES * sizeof(int), s2);
    hist_kernel<<<(E + 255) / 256, 256, 0, s2>>>(dst, E);
    invsqrt_kernel<<<(N + 255) / 256, 256, 0, s2>>>(N);
    blocksum_kernel<<<NBLK, 256, 0, s2>>>();
    bscan_kernel<<<1, 512, 0, s2>>>();
    offsets_kernel<<<NBLK, 256, 0, s2>>>();
    bin_kernel<<<(E + 255) / 256, 256, 0, s2>>>(src, dst, E);
    gstart_kernel<<<3, 256, 0, s2>>>(batch, N);
    cudaEventRecord(ev_join, s2);

    // ---- main stream: weight prep + encoder MLP ----
    {
        WPtrs wp;
        wp.w[0] = enc_W1; wp.w[1] = enc_W2;
        wp.w[2] = gcn_W;  wp.w[3] = gcn_W + WSZ; wp.w[4] = gcn_W + 2 * WSZ;
        wp.w[5] = dec_W1;
        prepw_kernel<<<NMAT * 64, 256>>>(wp);
    }
    mmagemm_kernel<0,false><<<gemm_blocks, 256, SMEM_BYTES>>>(
        x, whip + 0 * WSZ, wlop + 0 * WSZ, enc_b1, bufp, nullptr, N);
    mmagemm_kernel<0,false><<<gemm_blocks, 256, SMEM_BYTES>>>(
        bufp, whip + 1 * WSZ, wlop + 1 * WSZ, enc_b2, bufp, nullptr, N);

    // join: GCN gather needs g_inv/g_csr
    cudaStreamWaitEvent(0, ev_join, 0);

    // ---- GCN layers: GEMM -> hwh(fp16); gather computes full agg (pure store)
    const int gather_blocks = (NNODES * 32 + 255) / 256;
    for (int l = 0; l < NLAYER; l++) {
        if (l == 0)
            mmagemm_kernel<1,false><<<gemm_blocks, 256, SMEM_BYTES>>>(
                bufp, whip + (2 + l) * WSZ, wlop + (2 + l) * WSZ,
                nullptr, nullptr, hwhp, N);
        else
            mmagemm_kernel<1,true><<<gemm_blocks, 256, SMEM_BYTES>>>(
                aggp, whip + (2 + l) * WSZ, wlop + (2 + l) * WSZ,
                nullptr, nullptr, hwhp, N);
        gather_kernel<<<gather_blocks, 256>>>(hwhp, aggp,
                                              gcn_b + (size_t)l * DIM);
    }

    // ---- global add pool + decoder ----
    pool_kernel<<<NGRAPH, 128>>>(aggp);
    mmagemm_kernel<0,false><<<(NGRAPH + 127) / 128, 256, SMEM_BYTES>>>(
        poolp, whip + 5 * WSZ, wlop + 5 * WSZ, dec_b1, dec1p, nullptr, NGRAPH);
    dec2_kernel<<<(NGRAPH * OUTD + 255) / 256, 256>>>(dec1p, dec_W2, dec_b2, (float*)d_out);
}